// round 3
// baseline (speedup 1.0000x reference)
#include <cuda_runtime.h>
#include <cstdint>

#define B_ 2
#define H_ 8
#define S_ 2048
#define D_ 64
#define BH_ (B_ * H_)
#define OUT_OFF ((size_t)B_ * H_ * S_ * D_)   // output tensor first, then weights

__device__ float g_bias_lut[H_ * 2 * S_];     // 8 * 4096

// ---- packed f32x2 helpers ---------------------------------------------------
__device__ __forceinline__ unsigned long long pk2(float lo, float hi) {
    unsigned long long r;
    asm("mov.b64 %0, {%1, %2};" : "=l"(r) : "f"(lo), "f"(hi));
    return r;
}
__device__ __forceinline__ void fma2(unsigned long long& d, unsigned long long a, unsigned long long b) {
    asm("fma.rn.f32x2 %0, %1, %2, %0;" : "+l"(d) : "l"(a), "l"(b));
}
__device__ __forceinline__ void upk2(unsigned long long v, float& lo, float& hi) {
    asm("mov.b64 {%0, %1}, %2;" : "=f"(lo), "=f"(hi) : "l"(v));
}

// swizzle: 4-float granularity, keyed by kk's bits [2:5)
#define SWZ4(kk) ((((kk) >> 2) & 7) * 4)

// ---------------------------------------------------------------------------
// Kernel 0: T5 relative-position bias LUT (exact integer bucket thresholds)
// ---------------------------------------------------------------------------
__global__ void bias_lut_kernel(const float* __restrict__ bias_table) {
    int idx = blockIdx.x * blockDim.x + threadIdx.x;
    if (idx >= H_ * 2 * S_) return;
    int h   = idx >> 12;
    int r   = idx & 4095;
    int rel = r - 2048;
    int bucket = (rel > 0) ? 16 : 0;
    int a = rel < 0 ? -rel : rel;
    int add;
    if      (a <  8) add = a;
    else if (a < 12) add = 8;
    else if (a < 16) add = 9;
    else if (a < 23) add = 10;
    else if (a < 32) add = 11;
    else if (a < 46) add = 12;
    else if (a < 64) add = 13;
    else if (a < 91) add = 14;
    else             add = 15;
    g_bias_lut[idx] = bias_table[(bucket + add) * H_ + h];
}

// ---------------------------------------------------------------------------
// Kernel 1: logits = Q K^T / 8 + bias + mask*-1e9.
// 128x128 tile, 256 threads. Thread covers rows {ty*4..+3, +64} x cols
// {tx*4..+3, +64} (conflict-free LDS128). D chunked 2x32 -> 32KB smem.
// ---------------------------------------------------------------------------
__global__ __launch_bounds__(256) void logits_kernel(
    const float* __restrict__ Q, const float* __restrict__ K,
    const int* __restrict__ mask, float* __restrict__ out)
{
    extern __shared__ float smem[];
    float* Qs = smem;                 // [32][128]  (kk-chunk x row^swz)
    float* Ks = smem + 32 * 128;      // [32][128]

    int bh = blockIdx.z;
    int q0 = blockIdx.y * 128;
    int k0 = blockIdx.x * 128;
    int b  = bh >> 3;
    int h  = bh & 7;

    const float* Qp = Q + (size_t)bh * S_ * D_;
    const float* Kp = K + (size_t)bh * S_ * D_;

    int t  = threadIdx.x;
    int tx = t & 15, ty = t >> 4;     // ty 0..15

    unsigned long long acc2[8][4];
    #pragma unroll
    for (int i = 0; i < 8; i++)
        #pragma unroll
        for (int j = 0; j < 4; j++) acc2[i][j] = 0ULL;

    #pragma unroll
    for (int dc = 0; dc < 64; dc += 32) {
        // load 128 rows x 32 d, transposed with swizzle
        #pragma unroll
        for (int i = 0; i < 4; i++) {
            int idx4 = t + i * 256;           // 0..1023
            int row = idx4 >> 3;              // 0..127
            int c4  = idx4 & 7;               // d-segment in chunk
            float4 qv = *(const float4*)&Qp[(size_t)(q0 + row) * D_ + dc + c4 * 4];
            float4 kv = *(const float4*)&Kp[(size_t)(k0 + row) * D_ + dc + c4 * 4];
            #pragma unroll
            for (int j = 0; j < 4; j++) {
                int kk = c4 * 4 + j;          // 0..31
                int pc = row ^ SWZ4(kk);
                float qf = j == 0 ? qv.x : j == 1 ? qv.y : j == 2 ? qv.z : qv.w;
                float kf = j == 0 ? kv.x : j == 1 ? kv.y : j == 2 ? kv.z : kv.w;
                Qs[kk * 128 + pc] = qf;
                Ks[kk * 128 + pc] = kf;
            }
        }
        __syncthreads();

        #pragma unroll 8
        for (int kk = 0; kk < 32; kk++) {
            int swz = SWZ4(kk);
            int ab = (ty * 4) ^ swz;
            int bb = (tx * 4) ^ swz;
            float4 a0 = *(const float4*)&Qs[kk * 128 + ab];
            float4 a1 = *(const float4*)&Qs[kk * 128 + ab + 64];
            float4 b0 = *(const float4*)&Ks[kk * 128 + bb];
            float4 b1 = *(const float4*)&Ks[kk * 128 + bb + 64];
            unsigned long long bp[4] = { pk2(b0.x, b0.y), pk2(b0.z, b0.w),
                                         pk2(b1.x, b1.y), pk2(b1.z, b1.w) };
            float av[8] = {a0.x, a0.y, a0.z, a0.w, a1.x, a1.y, a1.z, a1.w};
            #pragma unroll
            for (int i = 0; i < 8; i++) {
                unsigned long long ad = pk2(av[i], av[i]);
                fma2(acc2[i][0], ad, bp[0]);
                fma2(acc2[i][1], ad, bp[1]);
                fma2(acc2[i][2], ad, bp[2]);
                fma2(acc2[i][3], ad, bp[3]);
            }
        }
        __syncthreads();
    }

    // epilogue
    int kb = k0 + tx * 4;
    float mv[8];
    #pragma unroll
    for (int j = 0; j < 4; j++) {
        mv[j]     = -1e9f * (float)mask[b * S_ + kb + j];
        mv[4 + j] = -1e9f * (float)mask[b * S_ + kb + 64 + j];
    }

    float* wbase = out + OUT_OFF + (size_t)bh * S_ * S_;
    const float* lut = g_bias_lut + h * 4096;
    #pragma unroll
    for (int ih = 0; ih < 2; ih++) {
        #pragma unroll
        for (int ii = 0; ii < 4; ii++) {
            int i = ih * 4 + ii;
            int q = q0 + ih * 64 + ty * 4 + ii;
            float c[8];
            #pragma unroll
            for (int j = 0; j < 4; j++) upk2(acc2[i][j], c[2 * j], c[2 * j + 1]);
            float4 v0, v1;
            v0.x = c[0] * 0.125f + lut[kb + 0 - q + 2048] + mv[0];
            v0.y = c[1] * 0.125f + lut[kb + 1 - q + 2048] + mv[1];
            v0.z = c[2] * 0.125f + lut[kb + 2 - q + 2048] + mv[2];
            v0.w = c[3] * 0.125f + lut[kb + 3 - q + 2048] + mv[3];
            v1.x = c[4] * 0.125f + lut[kb + 64 - q + 2048] + mv[4];
            v1.y = c[5] * 0.125f + lut[kb + 65 - q + 2048] + mv[5];
            v1.z = c[6] * 0.125f + lut[kb + 66 - q + 2048] + mv[6];
            v1.w = c[7] * 0.125f + lut[kb + 67 - q + 2048] + mv[7];
            *(float4*)&wbase[(size_t)q * S_ + kb]      = v0;
            *(float4*)&wbase[(size_t)q * S_ + kb + 64] = v1;
        }
    }
}

// ---------------------------------------------------------------------------
// fast exp: polynomial 2^f + exponent-bit scalbn. All FMA/ALU pipe, no MUFU.
// Valid for x <= ~0 (softmax post-max-subtract); clamps underflow.
// ---------------------------------------------------------------------------
__device__ __forceinline__ float fast_exp(float x) {
    x = fmaxf(x, -87.0f);
    float y = x * 1.4426950408889634f;
    float n = rintf(y);
    float f = y - n;
    float p = 1.5403530e-4f;
    p = fmaf(p, f, 1.3333558e-3f);
    p = fmaf(p, f, 9.6181291e-3f);
    p = fmaf(p, f, 5.5504109e-2f);
    p = fmaf(p, f, 2.4022651e-1f);
    p = fmaf(p, f, 6.9314718e-1f);
    p = fmaf(p, f, 1.0f);
    int e = (int)n;
    return p * __int_as_float((e + 127) << 23);
}

// ---------------------------------------------------------------------------
// Kernel 2: in-place row softmax (2048-wide rows), one 256-thread block/row.
// ---------------------------------------------------------------------------
__global__ __launch_bounds__(256) void softmax_kernel(float* __restrict__ w)
{
    __shared__ float redmax[8];
    __shared__ float redsum[8];

    float* p = w + OUT_OFF + (size_t)blockIdx.x * S_;
    int t = threadIdx.x;

    float4 v0 = reinterpret_cast<float4*>(p)[t];
    float4 v1 = reinterpret_cast<float4*>(p)[t + 256];

    float m = fmaxf(fmaxf(fmaxf(v0.x, v0.y), fmaxf(v0.z, v0.w)),
                    fmaxf(fmaxf(v1.x, v1.y), fmaxf(v1.z, v1.w)));
    #pragma unroll
    for (int o = 16; o; o >>= 1) m = fmaxf(m, __shfl_xor_sync(0xffffffffu, m, o));
    if ((t & 31) == 0) redmax[t >> 5] = m;
    __syncthreads();
    m = redmax[0];
    #pragma unroll
    for (int i = 1; i < 8; i++) m = fmaxf(m, redmax[i]);

    v0.x = fast_exp(v0.x - m); v0.y = fast_exp(v0.y - m);
    v0.z = fast_exp(v0.z - m); v0.w = fast_exp(v0.w - m);
    v1.x = fast_exp(v1.x - m); v1.y = fast_exp(v1.y - m);
    v1.z = fast_exp(v1.z - m); v1.w = fast_exp(v1.w - m);

    float s = (v0.x + v0.y) + (v0.z + v0.w) + (v1.x + v1.y) + (v1.z + v1.w);
    #pragma unroll
    for (int o = 16; o; o >>= 1) s += __shfl_xor_sync(0xffffffffu, s, o);
    if ((t & 31) == 0) redsum[t >> 5] = s;
    __syncthreads();
    s = 0.f;
    #pragma unroll
    for (int i = 0; i < 8; i++) s += redsum[i];

    float inv = 1.0f / s;
    v0.x *= inv; v0.y *= inv; v0.z *= inv; v0.w *= inv;
    v1.x *= inv; v1.y *= inv; v1.z *= inv; v1.w *= inv;

    reinterpret_cast<float4*>(p)[t]       = v0;
    reinterpret_cast<float4*>(p)[t + 256] = v1;
}

// ---------------------------------------------------------------------------
// Kernel 3: output = P @ V. 64x64 output tile, 256 threads split into two
// 128-thread halves that each own half of K=2048 (private 32KB tiles), then
// smem reduction. 8x4 per thread, f32x2 FMAs.
// ---------------------------------------------------------------------------
__global__ __launch_bounds__(256) void av_kernel(
    const float* __restrict__ W, const float* __restrict__ V, float* __restrict__ out)
{
    extern __shared__ float sm[];     // [half][Ps 4096 | Vs 4096] = 16384 floats

    int t    = threadIdx.x;
    int half = t >> 7;
    int tl   = t & 127;
    int tx = tl & 15, ty = tl >> 4;   // ty 0..7

    int bh = blockIdx.y;
    int q0 = blockIdx.x * 64;

    const float* Wp = W + OUT_OFF + (size_t)bh * S_ * S_;
    const float* Vp = V + (size_t)bh * S_ * D_;

    float* Ps = sm + half * 8192;
    float* Vs = Ps + 4096;

    unsigned long long acc2[8][2];
    #pragma unroll
    for (int i = 0; i < 8; i++) { acc2[i][0] = 0ULL; acc2[i][1] = 0ULL; }

    int kc_beg = half * (S_ / 2);
    for (int kc = kc_beg; kc < kc_beg + S_ / 2; kc += 64) {
        #pragma unroll
        for (int i = 0; i < 8; i++) {
            int idx4 = tl + i * 128;
            int r  = idx4 >> 4;           // 0..63
            int c4 = idx4 & 15;
            float4 wv = *(const float4*)&Wp[(size_t)(q0 + r) * S_ + kc + c4 * 4];
            #pragma unroll
            for (int j = 0; j < 4; j++) {
                int kk = c4 * 4 + j;
                float f = j == 0 ? wv.x : j == 1 ? wv.y : j == 2 ? wv.z : wv.w;
                Ps[kk * 64 + (r ^ SWZ4(kk))] = f;
            }
            *(float4*)&Vs[r * 64 + c4 * 4] =
                *(const float4*)&Vp[(size_t)(kc + r) * D_ + c4 * 4];
        }
        __syncthreads();

        #pragma unroll 8
        for (int kk = 0; kk < 64; kk++) {
            int swz = SWZ4(kk);
            float4 a0 = *(const float4*)&Ps[kk * 64 + ((ty * 8) ^ swz)];
            float4 a1 = *(const float4*)&Ps[kk * 64 + ((ty * 8 + 4) ^ swz)];
            float4 bv = *(const float4*)&Vs[kk * 64 + tx * 4];
            unsigned long long bp0 = pk2(bv.x, bv.y);
            unsigned long long bp1 = pk2(bv.z, bv.w);
            float av[8] = {a0.x, a0.y, a0.z, a0.w, a1.x, a1.y, a1.z, a1.w};
            #pragma unroll
            for (int i = 0; i < 8; i++) {
                unsigned long long ad = pk2(av[i], av[i]);
                fma2(acc2[i][0], ad, bp0);
                fma2(acc2[i][1], ad, bp1);
            }
        }
        __syncthreads();
    }

    // cross-half reduction via smem (reuse sm[0:4096])
    if (half == 1) {
        #pragma unroll
        for (int i = 0; i < 8; i++) {
            float4 v;
            upk2(acc2[i][0], v.x, v.y);
            upk2(acc2[i][1], v.z, v.w);
            *(float4*)&sm[(ty * 8 + i) * 64 + tx * 4] = v;
        }
    }
    __syncthreads();
    if (half == 0) {
        #pragma unroll
        for (int i = 0; i < 8; i++) {
            int q = q0 + ty * 8 + i;
            float4 r = *(float4*)&sm[(ty * 8 + i) * 64 + tx * 4];
            float4 v;
            upk2(acc2[i][0], v.x, v.y);
            upk2(acc2[i][1], v.z, v.w);
            v.x += r.x; v.y += r.y; v.z += r.z; v.w += r.w;
            *(float4*)&out[((size_t)bh * S_ + q) * D_ + tx * 4] = v;
        }
    }
}

// ---------------------------------------------------------------------------
extern "C" void kernel_launch(void* const* d_in, const int* in_sizes, int n_in,
                              void* d_out, int out_size)
{
    const float* Q    = (const float*)d_in[0];
    const float* K    = (const float*)d_in[1];
    const float* V    = (const float*)d_in[2];
    const int*   mask = (const int*)d_in[3];
    const float* bt   = (const float*)d_in[4];
    float* out = (float*)d_out;

    cudaFuncSetAttribute(av_kernel, cudaFuncAttributeMaxDynamicSharedMemorySize, 65536);

    bias_lut_kernel<<<32, 1024>>>(bt);

    dim3 g1(S_ / 128, S_ / 128, BH_);   // (16, 16, 16)
    logits_kernel<<<g1, 256, 32768>>>(Q, K, mask, out);

    softmax_kernel<<<BH_ * S_, 256>>>(out);

    dim3 g2(S_ / 64, BH_);              // (32, 16)
    av_kernel<<<g2, 256, 65536>>>(out, V, out);
}

// round 4
// speedup vs baseline: 1.1606x; 1.1606x over previous
#include <cuda_runtime.h>
#include <cstdint>

#define B_ 2
#define H_ 8
#define S_ 2048
#define D_ 64
#define BH_ (B_ * H_)
#define OUT_OFF ((size_t)B_ * H_ * S_ * D_)   // output tensor first, then weights

__device__ float g_bias_lut[H_ * 2 * S_];     // 8 * 4096

// ---- tf32 mma helpers -------------------------------------------------------
__device__ __forceinline__ unsigned f2tf(float f) {
    unsigned u;
    asm("cvt.rna.tf32.f32 %0, %1;" : "=r"(u) : "f"(f));
    return u;
}
__device__ __forceinline__ void split_tf(float f, unsigned& hi, unsigned& lo) {
    hi = f2tf(f);
    lo = f2tf(f - __uint_as_float(hi));
}
__device__ __forceinline__ void mma8(float* d, const unsigned* a, const unsigned* b) {
    asm("mma.sync.aligned.m16n8k8.row.col.f32.tf32.tf32.f32 "
        "{%0,%1,%2,%3},{%4,%5,%6,%7},{%8,%9},{%0,%1,%2,%3};"
        : "+f"(d[0]), "+f"(d[1]), "+f"(d[2]), "+f"(d[3])
        : "r"(a[0]), "r"(a[1]), "r"(a[2]), "r"(a[3]), "r"(b[0]), "r"(b[1]));
}

// ---------------------------------------------------------------------------
// Kernel 0: T5 relative-position bias LUT (exact integer bucket thresholds)
// ---------------------------------------------------------------------------
__global__ void bias_lut_kernel(const float* __restrict__ bias_table) {
    int idx = blockIdx.x * blockDim.x + threadIdx.x;
    if (idx >= H_ * 2 * S_) return;
    int h   = idx >> 12;
    int r   = idx & 4095;
    int rel = r - 2048;
    int bucket = (rel > 0) ? 16 : 0;
    int a = rel < 0 ? -rel : rel;
    int add;
    if      (a <  8) add = a;
    else if (a < 12) add = 8;
    else if (a < 16) add = 9;
    else if (a < 23) add = 10;
    else if (a < 32) add = 11;
    else if (a < 46) add = 12;
    else if (a < 64) add = 13;
    else if (a < 91) add = 14;
    else             add = 15;
    g_bias_lut[idx] = bias_table[(bucket + add) * H_ + h];
}

// ---------------------------------------------------------------------------
// Kernel 1: logits = Q K^T / 8 + bias + mask*-1e9 via tf32 mma (3xTF32).
// Block tile 128(M q) x 64(N k), 8 warps (4x2), warp tile 32x32.
// Qs[128][68] (row=q, col=d), Ks[64][68] (row=k, col=d) -- both are the
// natural global layouts (A row-major, B "col"-major == K's [seq][d]).
// ---------------------------------------------------------------------------
__global__ __launch_bounds__(256) void logits_kernel(
    const float* __restrict__ Q, const float* __restrict__ K,
    const int* __restrict__ mask, float* __restrict__ out)
{
    extern __shared__ float smem[];
    float* Qs = smem;               // [128][68]
    float* Ks = smem + 128 * 68;    // [64][68]

    int bh = blockIdx.z;
    int q0 = blockIdx.y * 128;
    int k0 = blockIdx.x * 64;
    int b  = bh >> 3;
    int h  = bh & 7;

    const float* Qp = Q + (size_t)bh * S_ * D_;
    const float* Kp = K + (size_t)bh * S_ * D_;

    int t = threadIdx.x;
    #pragma unroll
    for (int i = 0; i < 8; i++) {
        int idx = t + i * 256;
        int r = idx >> 4, c4 = idx & 15;
        *(float4*)&Qs[r * 68 + c4 * 4] = *(const float4*)&Qp[(size_t)(q0 + r) * D_ + c4 * 4];
    }
    #pragma unroll
    for (int i = 0; i < 4; i++) {
        int idx = t + i * 256;
        int n = idx >> 4, c4 = idx & 15;
        *(float4*)&Ks[n * 68 + c4 * 4] = *(const float4*)&Kp[(size_t)(k0 + n) * D_ + c4 * 4];
    }
    __syncthreads();

    int w = t >> 5, l = t & 31, g = l >> 2, tg = l & 3;
    int wm = w & 3, wn = w >> 2;

    float C[2][4][4] = {};

    #pragma unroll
    for (int ks = 0; ks < 8; ks++) {
        int kb = ks * 8;
        unsigned ah[2][4], al[2][4];
        #pragma unroll
        for (int mt = 0; mt < 2; mt++) {
            int r0 = wm * 32 + mt * 16 + g;
            split_tf(Qs[r0 * 68 + kb + tg],           ah[mt][0], al[mt][0]);
            split_tf(Qs[(r0 + 8) * 68 + kb + tg],     ah[mt][1], al[mt][1]);
            split_tf(Qs[r0 * 68 + kb + tg + 4],       ah[mt][2], al[mt][2]);
            split_tf(Qs[(r0 + 8) * 68 + kb + tg + 4], ah[mt][3], al[mt][3]);
        }
        unsigned bh_[4][2], bl_[4][2];
        #pragma unroll
        for (int nt = 0; nt < 4; nt++) {
            int n = wn * 32 + nt * 8 + g;
            split_tf(Ks[n * 68 + kb + tg],     bh_[nt][0], bl_[nt][0]);
            split_tf(Ks[n * 68 + kb + tg + 4], bh_[nt][1], bl_[nt][1]);
        }
        #pragma unroll
        for (int mt = 0; mt < 2; mt++)
            #pragma unroll
            for (int nt = 0; nt < 4; nt++) {
                mma8(C[mt][nt], ah[mt], bh_[nt]);
                mma8(C[mt][nt], ah[mt], bl_[nt]);
                mma8(C[mt][nt], al[mt], bh_[nt]);
            }
    }

    // epilogue: scale + bias + mask, float2 stores
    float* wbase = out + OUT_OFF + (size_t)bh * S_ * S_;
    const float* lut = g_bias_lut + h * 4096;
    #pragma unroll
    for (int nt = 0; nt < 4; nt++) {
        int kcol = k0 + wn * 32 + nt * 8 + 2 * tg;
        float mv0 = -1e9f * (float)mask[b * S_ + kcol];
        float mv1 = -1e9f * (float)mask[b * S_ + kcol + 1];
        #pragma unroll
        for (int mt = 0; mt < 2; mt++) {
            int q = q0 + wm * 32 + mt * 16 + g;
            float2 v;
            v.x = C[mt][nt][0] * 0.125f + lut[kcol     - q + 2048] + mv0;
            v.y = C[mt][nt][1] * 0.125f + lut[kcol + 1 - q + 2048] + mv1;
            *(float2*)&wbase[(size_t)q * S_ + kcol] = v;
            int q2 = q + 8;
            v.x = C[mt][nt][2] * 0.125f + lut[kcol     - q2 + 2048] + mv0;
            v.y = C[mt][nt][3] * 0.125f + lut[kcol + 1 - q2 + 2048] + mv1;
            *(float2*)&wbase[(size_t)q2 * S_ + kcol] = v;
        }
    }
}

// ---------------------------------------------------------------------------
// fast exp (FMA pipe only, no MUFU) for x <= 0 range with underflow clamp
// ---------------------------------------------------------------------------
__device__ __forceinline__ float fast_exp(float x) {
    x = fmaxf(x, -87.0f);
    float y = x * 1.4426950408889634f;
    float n = rintf(y);
    float f = y - n;
    float p = 1.5403530e-4f;
    p = fmaf(p, f, 1.3333558e-3f);
    p = fmaf(p, f, 9.6181291e-3f);
    p = fmaf(p, f, 5.5504109e-2f);
    p = fmaf(p, f, 2.4022651e-1f);
    p = fmaf(p, f, 6.9314718e-1f);
    p = fmaf(p, f, 1.0f);
    int e = (int)n;
    return p * __int_as_float((e + 127) << 23);
}

// ---------------------------------------------------------------------------
// Kernel 2: in-place row softmax (2048-wide rows), one 256-thread block/row.
// ---------------------------------------------------------------------------
__global__ __launch_bounds__(256) void softmax_kernel(float* __restrict__ w)
{
    __shared__ float redmax[8];
    __shared__ float redsum[8];

    float* p = w + OUT_OFF + (size_t)blockIdx.x * S_;
    int t = threadIdx.x;

    float4 v0 = reinterpret_cast<float4*>(p)[t];
    float4 v1 = reinterpret_cast<float4*>(p)[t + 256];

    float m = fmaxf(fmaxf(fmaxf(v0.x, v0.y), fmaxf(v0.z, v0.w)),
                    fmaxf(fmaxf(v1.x, v1.y), fmaxf(v1.z, v1.w)));
    #pragma unroll
    for (int o = 16; o; o >>= 1) m = fmaxf(m, __shfl_xor_sync(0xffffffffu, m, o));
    if ((t & 31) == 0) redmax[t >> 5] = m;
    __syncthreads();
    m = redmax[0];
    #pragma unroll
    for (int i = 1; i < 8; i++) m = fmaxf(m, redmax[i]);

    v0.x = fast_exp(v0.x - m); v0.y = fast_exp(v0.y - m);
    v0.z = fast_exp(v0.z - m); v0.w = fast_exp(v0.w - m);
    v1.x = fast_exp(v1.x - m); v1.y = fast_exp(v1.y - m);
    v1.z = fast_exp(v1.z - m); v1.w = fast_exp(v1.w - m);

    float s = (v0.x + v0.y) + (v0.z + v0.w) + (v1.x + v1.y) + (v1.z + v1.w);
    #pragma unroll
    for (int o = 16; o; o >>= 1) s += __shfl_xor_sync(0xffffffffu, s, o);
    if ((t & 31) == 0) redsum[t >> 5] = s;
    __syncthreads();
    s = 0.f;
    #pragma unroll
    for (int i = 0; i < 8; i++) s += redsum[i];

    float inv = 1.0f / s;
    v0.x *= inv; v0.y *= inv; v0.z *= inv; v0.w *= inv;
    v1.x *= inv; v1.y *= inv; v1.z *= inv; v1.w *= inv;

    reinterpret_cast<float4*>(p)[t]       = v0;
    reinterpret_cast<float4*>(p)[t + 256] = v1;
}

// ---------------------------------------------------------------------------
// Kernel 3: output = P @ V via tf32 mma (3xTF32).
// Block tile 64(M q) x 64(N d), 8 warps (4x2), warp tile 16x32, K chunk 64.
// Ps[64][68] (row=q, col=kseq), Vs[64][68] (row=kseq, col=d).
// ---------------------------------------------------------------------------
__global__ __launch_bounds__(256) void av_kernel(
    const float* __restrict__ W, const float* __restrict__ V, float* __restrict__ out)
{
    extern __shared__ float smem[];
    float* Ps = smem;              // [64][68]
    float* Vs = smem + 64 * 68;    // [64][68]

    int bh = blockIdx.y;
    int q0 = blockIdx.x * 64;

    const float* Wp = W + OUT_OFF + (size_t)bh * S_ * S_;
    const float* Vp = V + (size_t)bh * S_ * D_;

    int t = threadIdx.x;
    int w = t >> 5, l = t & 31, g = l >> 2, tg = l & 3;
    int wm = w & 3, wn = w >> 2;

    float C[4][4] = {};

    for (int kc = 0; kc < S_; kc += 64) {
        #pragma unroll
        for (int i = 0; i < 4; i++) {
            int idx = t + i * 256;
            int r = idx >> 4, c4 = idx & 15;
            *(float4*)&Ps[r * 68 + c4 * 4] = *(const float4*)&Wp[(size_t)(q0 + r) * S_ + kc + c4 * 4];
            *(float4*)&Vs[r * 68 + c4 * 4] = *(const float4*)&Vp[(size_t)(kc + r) * D_ + c4 * 4];
        }
        __syncthreads();

        #pragma unroll
        for (int ks = 0; ks < 8; ks++) {
            int kb = ks * 8;
            int r0 = wm * 16 + g;
            unsigned ah[4], al[4];
            split_tf(Ps[r0 * 68 + kb + tg],           ah[0], al[0]);
            split_tf(Ps[(r0 + 8) * 68 + kb + tg],     ah[1], al[1]);
            split_tf(Ps[r0 * 68 + kb + tg + 4],       ah[2], al[2]);
            split_tf(Ps[(r0 + 8) * 68 + kb + tg + 4], ah[3], al[3]);
            #pragma unroll
            for (int nt = 0; nt < 4; nt++) {
                int n = wn * 32 + nt * 8 + g;
                unsigned bhr[2], blr[2];
                split_tf(Vs[(kb + tg) * 68 + n],     bhr[0], blr[0]);
                split_tf(Vs[(kb + tg + 4) * 68 + n], bhr[1], blr[1]);
                mma8(C[nt], ah, bhr);
                mma8(C[nt], ah, blr);
                mma8(C[nt], al, bhr);
            }
        }
        __syncthreads();
    }

    #pragma unroll
    for (int nt = 0; nt < 4; nt++) {
        int d = wn * 32 + nt * 8 + 2 * tg;
        int q = q0 + wm * 16 + g;
        *(float2*)&out[((size_t)bh * S_ + q) * D_ + d]     = make_float2(C[nt][0], C[nt][1]);
        *(float2*)&out[((size_t)bh * S_ + q + 8) * D_ + d] = make_float2(C[nt][2], C[nt][3]);
    }
}

// ---------------------------------------------------------------------------
extern "C" void kernel_launch(void* const* d_in, const int* in_sizes, int n_in,
                              void* d_out, int out_size)
{
    const float* Q    = (const float*)d_in[0];
    const float* K    = (const float*)d_in[1];
    const float* V    = (const float*)d_in[2];
    const int*   mask = (const int*)d_in[3];
    const float* bt   = (const float*)d_in[4];
    float* out = (float*)d_out;

    const int logits_smem = (128 * 68 + 64 * 68) * 4;   // 52224
    const int av_smem     = (64 * 68 * 2) * 4;          // 34816
    cudaFuncSetAttribute(logits_kernel, cudaFuncAttributeMaxDynamicSharedMemorySize, logits_smem);
    cudaFuncSetAttribute(av_kernel,     cudaFuncAttributeMaxDynamicSharedMemorySize, av_smem);

    bias_lut_kernel<<<32, 1024>>>(bt);

    dim3 g1(S_ / 64, S_ / 128, BH_);    // (32, 16, 16)
    logits_kernel<<<g1, 256, logits_smem>>>(Q, K, mask, out);

    softmax_kernel<<<BH_ * S_, 256>>>(out);

    dim3 g2(S_ / 64, BH_);              // (32, 16)
    av_kernel<<<g2, 256, av_smem>>>(out, V, out);
}

// round 5
// speedup vs baseline: 1.2157x; 1.0475x over previous
#include <cuda_runtime.h>
#include <cstdint>

#define B_ 2
#define H_ 8
#define S_ 2048
#define D_ 64
#define BH_ (B_ * H_)
#define OUT_OFF ((size_t)B_ * H_ * S_ * D_)   // output tensor first, then weights

__device__ float g_bias_lut[H_ * 2 * S_];     // 8 * 4096

// ---- tf32 helpers -----------------------------------------------------------
__device__ __forceinline__ unsigned f2tf(float f) {
    unsigned u;
    asm("cvt.rna.tf32.f32 %0, %1;" : "=r"(u) : "f"(f));
    return u;
}
// (hi, lo) both as tf32 bit patterns reinterpreted as float
__device__ __forceinline__ float2 split2(float f) {
    float fh = __uint_as_float(f2tf(f));
    float fl = __uint_as_float(f2tf(f - fh));
    return make_float2(fh, fl);
}
__device__ __forceinline__ void mma8(float* d, const unsigned* a, const unsigned* b) {
    asm("mma.sync.aligned.m16n8k8.row.col.f32.tf32.tf32.f32 "
        "{%0,%1,%2,%3},{%4,%5,%6,%7},{%8,%9},{%0,%1,%2,%3};"
        : "+f"(d[0]), "+f"(d[1]), "+f"(d[2]), "+f"(d[3])
        : "r"(a[0]), "r"(a[1]), "r"(a[2]), "r"(a[3]), "r"(b[0]), "r"(b[1]));
}

// ---------------------------------------------------------------------------
// Kernel 0: T5 relative-position bias LUT (exact integer bucket thresholds)
// ---------------------------------------------------------------------------
__global__ void bias_lut_kernel(const float* __restrict__ bias_table) {
    int idx = blockIdx.x * blockDim.x + threadIdx.x;
    if (idx >= H_ * 2 * S_) return;
    int h   = idx >> 12;
    int r   = idx & 4095;
    int rel = r - 2048;
    int bucket = (rel > 0) ? 16 : 0;
    int a = rel < 0 ? -rel : rel;
    int add;
    if      (a <  8) add = a;
    else if (a < 12) add = 8;
    else if (a < 16) add = 9;
    else if (a < 23) add = 10;
    else if (a < 32) add = 11;
    else if (a < 46) add = 12;
    else if (a < 64) add = 13;
    else if (a < 91) add = 14;
    else             add = 15;
    g_bias_lut[idx] = bias_table[(bucket + add) * H_ + h];
}

// ---------------------------------------------------------------------------
// Kernel 1: logits = Q K^T / 8 + bias + mask*-1e9 via tf32 mma, 3-pass,
// hi/lo pre-split into smem float2 planes.
// Tile 128(q) x 64(k), 8 warps (4x2), warp 32x32. d chunked 2x32.
// Qs2[128][36] f2 (stride 36 pairs => pair-bank = 4*g+tg, conflict-free),
// Ks2[64][36] f2.
// ---------------------------------------------------------------------------
#define QSTR 36
__global__ __launch_bounds__(256) void logits_kernel(
    const float* __restrict__ Q, const float* __restrict__ K,
    const int* __restrict__ mask, float* __restrict__ out)
{
    extern __shared__ float2 sm2[];
    float2* Qs2 = sm2;                   // [128][36]
    float2* Ks2 = sm2 + 128 * QSTR;      // [64][36]

    int bh = blockIdx.z;
    int q0 = blockIdx.y * 128;
    int k0 = blockIdx.x * 64;
    int b  = bh >> 3;
    int h  = bh & 7;

    const float* Qp = Q + (size_t)bh * S_ * D_;
    const float* Kp = K + (size_t)bh * S_ * D_;

    int t = threadIdx.x;
    int w = t >> 5, l = t & 31, g = l >> 2, tg = l & 3;
    int wm = w & 3, wn = w >> 2;

    float C[2][4][4] = {};

    #pragma unroll
    for (int dc = 0; dc < 64; dc += 32) {
        // fill Q: 128 rows x 32 d = 1024 float4
        #pragma unroll
        for (int i = 0; i < 4; i++) {
            int idx = t + i * 256;
            int r = idx >> 3, c4 = idx & 7;
            float4 qv = *(const float4*)&Qp[(size_t)(q0 + r) * D_ + dc + c4 * 4];
            Qs2[r * QSTR + c4 * 4 + 0] = split2(qv.x);
            Qs2[r * QSTR + c4 * 4 + 1] = split2(qv.y);
            Qs2[r * QSTR + c4 * 4 + 2] = split2(qv.z);
            Qs2[r * QSTR + c4 * 4 + 3] = split2(qv.w);
        }
        // fill K: 64 rows x 32 d = 512 float4
        #pragma unroll
        for (int i = 0; i < 2; i++) {
            int idx = t + i * 256;
            int n = idx >> 3, c4 = idx & 7;
            float4 kv = *(const float4*)&Kp[(size_t)(k0 + n) * D_ + dc + c4 * 4];
            Ks2[n * QSTR + c4 * 4 + 0] = split2(kv.x);
            Ks2[n * QSTR + c4 * 4 + 1] = split2(kv.y);
            Ks2[n * QSTR + c4 * 4 + 2] = split2(kv.z);
            Ks2[n * QSTR + c4 * 4 + 3] = split2(kv.w);
        }
        __syncthreads();

        #pragma unroll
        for (int ks = 0; ks < 4; ks++) {
            int kb = ks * 8;
            unsigned ah[2][4], al[2][4];
            #pragma unroll
            for (int mt = 0; mt < 2; mt++) {
                int r0 = wm * 32 + mt * 16 + g;
                float2 v0 = Qs2[r0 * QSTR + kb + tg];
                float2 v1 = Qs2[(r0 + 8) * QSTR + kb + tg];
                float2 v2 = Qs2[r0 * QSTR + kb + tg + 4];
                float2 v3 = Qs2[(r0 + 8) * QSTR + kb + tg + 4];
                ah[mt][0] = __float_as_uint(v0.x); al[mt][0] = __float_as_uint(v0.y);
                ah[mt][1] = __float_as_uint(v1.x); al[mt][1] = __float_as_uint(v1.y);
                ah[mt][2] = __float_as_uint(v2.x); al[mt][2] = __float_as_uint(v2.y);
                ah[mt][3] = __float_as_uint(v3.x); al[mt][3] = __float_as_uint(v3.y);
            }
            unsigned bhr[4][2], blr[4][2];
            #pragma unroll
            for (int nt = 0; nt < 4; nt++) {
                int n = wn * 32 + nt * 8 + g;
                float2 u0 = Ks2[n * QSTR + kb + tg];
                float2 u1 = Ks2[n * QSTR + kb + tg + 4];
                bhr[nt][0] = __float_as_uint(u0.x); blr[nt][0] = __float_as_uint(u0.y);
                bhr[nt][1] = __float_as_uint(u1.x); blr[nt][1] = __float_as_uint(u1.y);
            }
            #pragma unroll
            for (int mt = 0; mt < 2; mt++)
                #pragma unroll
                for (int nt = 0; nt < 4; nt++) {
                    mma8(C[mt][nt], ah[mt], bhr[nt]);
                    mma8(C[mt][nt], ah[mt], blr[nt]);
                    mma8(C[mt][nt], al[mt], bhr[nt]);
                }
        }
        __syncthreads();
    }

    // epilogue: scale + bias + mask, float2 stores
    float* wbase = out + OUT_OFF + (size_t)bh * S_ * S_;
    const float* lut = g_bias_lut + h * 4096;
    #pragma unroll
    for (int nt = 0; nt < 4; nt++) {
        int kcol = k0 + wn * 32 + nt * 8 + 2 * tg;
        float mv0 = -1e9f * (float)mask[b * S_ + kcol];
        float mv1 = -1e9f * (float)mask[b * S_ + kcol + 1];
        #pragma unroll
        for (int mt = 0; mt < 2; mt++) {
            int q = q0 + wm * 32 + mt * 16 + g;
            float2 v;
            v.x = C[mt][nt][0] * 0.125f + lut[kcol     - q + 2048] + mv0;
            v.y = C[mt][nt][1] * 0.125f + lut[kcol + 1 - q + 2048] + mv1;
            *(float2*)&wbase[(size_t)q * S_ + kcol] = v;
            int q2 = q + 8;
            v.x = C[mt][nt][2] * 0.125f + lut[kcol     - q2 + 2048] + mv0;
            v.y = C[mt][nt][3] * 0.125f + lut[kcol + 1 - q2 + 2048] + mv1;
            *(float2*)&wbase[(size_t)q2 * S_ + kcol] = v;
        }
    }
}

// ---------------------------------------------------------------------------
// fast exp (FMA pipe only, no MUFU) for x <= 0 range with underflow clamp
// ---------------------------------------------------------------------------
__device__ __forceinline__ float fast_exp(float x) {
    x = fmaxf(x, -87.0f);
    float y = x * 1.4426950408889634f;
    float n = rintf(y);
    float f = y - n;
    float p = 1.5403530e-4f;
    p = fmaf(p, f, 1.3333558e-3f);
    p = fmaf(p, f, 9.6181291e-3f);
    p = fmaf(p, f, 5.5504109e-2f);
    p = fmaf(p, f, 2.4022651e-1f);
    p = fmaf(p, f, 6.9314718e-1f);
    p = fmaf(p, f, 1.0f);
    int e = (int)n;
    return p * __int_as_float((e + 127) << 23);
}

// ---------------------------------------------------------------------------
// Kernel 2: in-place row softmax (2048-wide rows), one 256-thread block/row.
// ---------------------------------------------------------------------------
__global__ __launch_bounds__(256) void softmax_kernel(float* __restrict__ w)
{
    __shared__ float redmax[8];
    __shared__ float redsum[8];

    float* p = w + OUT_OFF + (size_t)blockIdx.x * S_;
    int t = threadIdx.x;

    float4 v0 = reinterpret_cast<float4*>(p)[t];
    float4 v1 = reinterpret_cast<float4*>(p)[t + 256];

    float m = fmaxf(fmaxf(fmaxf(v0.x, v0.y), fmaxf(v0.z, v0.w)),
                    fmaxf(fmaxf(v1.x, v1.y), fmaxf(v1.z, v1.w)));
    #pragma unroll
    for (int o = 16; o; o >>= 1) m = fmaxf(m, __shfl_xor_sync(0xffffffffu, m, o));
    if ((t & 31) == 0) redmax[t >> 5] = m;
    __syncthreads();
    m = redmax[0];
    #pragma unroll
    for (int i = 1; i < 8; i++) m = fmaxf(m, redmax[i]);

    v0.x = fast_exp(v0.x - m); v0.y = fast_exp(v0.y - m);
    v0.z = fast_exp(v0.z - m); v0.w = fast_exp(v0.w - m);
    v1.x = fast_exp(v1.x - m); v1.y = fast_exp(v1.y - m);
    v1.z = fast_exp(v1.z - m); v1.w = fast_exp(v1.w - m);

    float s = (v0.x + v0.y) + (v0.z + v0.w) + (v1.x + v1.y) + (v1.z + v1.w);
    #pragma unroll
    for (int o = 16; o; o >>= 1) s += __shfl_xor_sync(0xffffffffu, s, o);
    if ((t & 31) == 0) redsum[t >> 5] = s;
    __syncthreads();
    s = 0.f;
    #pragma unroll
    for (int i = 0; i < 8; i++) s += redsum[i];

    float inv = 1.0f / s;
    v0.x *= inv; v0.y *= inv; v0.z *= inv; v0.w *= inv;
    v1.x *= inv; v1.y *= inv; v1.z *= inv; v1.w *= inv;

    reinterpret_cast<float4*>(p)[t]       = v0;
    reinterpret_cast<float4*>(p)[t + 256] = v1;
}

// ---------------------------------------------------------------------------
// Kernel 3: output = P @ V via tf32 mma, 2-pass (P split hi/lo, V single tf32).
// Block 64(q) x 64(d), 8 warps (4x2), warp 16x32, K chunk 64.
// Ps2[64][68] f2 (pair-stride 68 => 4g+tg banks, conflict-free),
// Vs[64][72] f32 (stride 72 => 8*tg+g banks for B frags, conflict-free).
// ---------------------------------------------------------------------------
#define PSTR 68
#define VSTR 72
__global__ __launch_bounds__(256) void av_kernel(
    const float* __restrict__ W, const float* __restrict__ V, float* __restrict__ out)
{
    extern __shared__ float2 sm2[];
    float2* Ps2 = sm2;                        // [64][68]
    float*  Vs  = (float*)(sm2 + 64 * PSTR);  // [64][72]

    int bh = blockIdx.y;
    int q0 = blockIdx.x * 64;

    const float* Wp = W + OUT_OFF + (size_t)bh * S_ * S_;
    const float* Vp = V + (size_t)bh * S_ * D_;

    int t = threadIdx.x;
    int w = t >> 5, l = t & 31, g = l >> 2, tg = l & 3;
    int wm = w & 3, wn = w >> 2;

    float C[4][4] = {};

    for (int kc = 0; kc < S_; kc += 64) {
        #pragma unroll
        for (int i = 0; i < 4; i++) {
            int idx = t + i * 256;
            int r = idx >> 4, c4 = idx & 15;
            float4 wv = *(const float4*)&Wp[(size_t)(q0 + r) * S_ + kc + c4 * 4];
            Ps2[r * PSTR + c4 * 4 + 0] = split2(wv.x);
            Ps2[r * PSTR + c4 * 4 + 1] = split2(wv.y);
            Ps2[r * PSTR + c4 * 4 + 2] = split2(wv.z);
            Ps2[r * PSTR + c4 * 4 + 3] = split2(wv.w);

            float4 vv = *(const float4*)&Vp[(size_t)(kc + r) * D_ + c4 * 4];
            float4 vc;
            vc.x = __uint_as_float(f2tf(vv.x));
            vc.y = __uint_as_float(f2tf(vv.y));
            vc.z = __uint_as_float(f2tf(vv.z));
            vc.w = __uint_as_float(f2tf(vv.w));
            *(float4*)&Vs[r * VSTR + c4 * 4] = vc;
        }
        __syncthreads();

        #pragma unroll
        for (int ks = 0; ks < 8; ks++) {
            int kb = ks * 8;
            int r0 = wm * 16 + g;
            unsigned ah[4], al[4];
            float2 v0 = Ps2[r0 * PSTR + kb + tg];
            float2 v1 = Ps2[(r0 + 8) * PSTR + kb + tg];
            float2 v2 = Ps2[r0 * PSTR + kb + tg + 4];
            float2 v3 = Ps2[(r0 + 8) * PSTR + kb + tg + 4];
            ah[0] = __float_as_uint(v0.x); al[0] = __float_as_uint(v0.y);
            ah[1] = __float_as_uint(v1.x); al[1] = __float_as_uint(v1.y);
            ah[2] = __float_as_uint(v2.x); al[2] = __float_as_uint(v2.y);
            ah[3] = __float_as_uint(v3.x); al[3] = __float_as_uint(v3.y);
            #pragma unroll
            for (int nt = 0; nt < 4; nt++) {
                int n = wn * 32 + nt * 8 + g;
                unsigned bhr[2];
                bhr[0] = __float_as_uint(Vs[(kb + tg) * VSTR + n]);
                bhr[1] = __float_as_uint(Vs[(kb + tg + 4) * VSTR + n]);
                mma8(C[nt], ah, bhr);
                mma8(C[nt], al, bhr);
            }
        }
        __syncthreads();
    }

    #pragma unroll
    for (int nt = 0; nt < 4; nt++) {
        int d = wn * 32 + nt * 8 + 2 * tg;
        int q = q0 + wm * 16 + g;
        *(float2*)&out[((size_t)bh * S_ + q) * D_ + d]     = make_float2(C[nt][0], C[nt][1]);
        *(float2*)&out[((size_t)bh * S_ + q + 8) * D_ + d] = make_float2(C[nt][2], C[nt][3]);
    }
}

// ---------------------------------------------------------------------------
extern "C" void kernel_launch(void* const* d_in, const int* in_sizes, int n_in,
                              void* d_out, int out_size)
{
    const float* Q    = (const float*)d_in[0];
    const float* K    = (const float*)d_in[1];
    const float* V    = (const float*)d_in[2];
    const int*   mask = (const int*)d_in[3];
    const float* bt   = (const float*)d_in[4];
    float* out = (float*)d_out;

    const int logits_smem = (128 * QSTR + 64 * QSTR) * 8;       // 55296
    const int av_smem     = 64 * PSTR * 8 + 64 * VSTR * 4;      // 53248
    cudaFuncSetAttribute(logits_kernel, cudaFuncAttributeMaxDynamicSharedMemorySize, logits_smem);
    cudaFuncSetAttribute(av_kernel,     cudaFuncAttributeMaxDynamicSharedMemorySize, av_smem);

    bias_lut_kernel<<<32, 1024>>>(bt);

    dim3 g1(S_ / 64, S_ / 128, BH_);    // (32, 16, 16)
    logits_kernel<<<g1, 256, logits_smem>>>(Q, K, mask, out);

    softmax_kernel<<<BH_ * S_, 256>>>(out);

    dim3 g2(S_ / 64, BH_);              // (32, 16)
    av_kernel<<<g2, 256, av_smem>>>(out, V, out);
}

// round 6
// speedup vs baseline: 1.5411x; 1.2677x over previous
#include <cuda_runtime.h>
#include <cuda_bf16.h>
#include <cstdint>

#define B_ 2
#define H_ 8
#define S_ 2048
#define D_ 64
#define BH_ (B_ * H_)
#define OUT_OFF ((size_t)B_ * H_ * S_ * D_)   // output tensor first, then weights
#define KBLK 32                                // 2048/64 k-blocks per row

__device__ float  g_bias_lut[H_ * 2 * S_];            // 8 * 4096
__device__ float2 g_stats[BH_ * S_ * KBLK];           // per (row, kblock): (max, sumexp)  8MB
__device__ float2 g_rowstats[BH_ * S_];               // per row: (max, 1/sum)

// ---- bf16 split/pack helpers ------------------------------------------------
__device__ __forceinline__ void split_pack(float x0, float x1, unsigned& hi, unsigned& lo) {
    __nv_bfloat162 h = __floats2bfloat162_rn(x0, x1);
    float f0 = __bfloat162float(__low2bfloat16(h));
    float f1 = __bfloat162float(__high2bfloat16(h));
    __nv_bfloat162 l = __floats2bfloat162_rn(x0 - f0, x1 - f1);
    hi = *reinterpret_cast<unsigned*>(&h);
    lo = *reinterpret_cast<unsigned*>(&l);
}
__device__ __forceinline__ void mma16(float* d, const unsigned* a, const unsigned* b) {
    asm("mma.sync.aligned.m16n8k16.row.col.f32.bf16.bf16.f32 "
        "{%0,%1,%2,%3},{%4,%5,%6,%7},{%8,%9},{%0,%1,%2,%3};"
        : "+f"(d[0]), "+f"(d[1]), "+f"(d[2]), "+f"(d[3])
        : "r"(a[0]), "r"(a[1]), "r"(a[2]), "r"(a[3]), "r"(b[0]), "r"(b[1]));
}

// fast exp (FMA pipe only), valid for x <= 0, underflow clamp
__device__ __forceinline__ float fast_exp(float x) {
    x = fmaxf(x, -87.0f);
    float y = x * 1.4426950408889634f;
    float n = rintf(y);
    float f = y - n;
    float p = 1.5403530e-4f;
    p = fmaf(p, f, 1.3333558e-3f);
    p = fmaf(p, f, 9.6181291e-3f);
    p = fmaf(p, f, 5.5504109e-2f);
    p = fmaf(p, f, 2.4022651e-1f);
    p = fmaf(p, f, 6.9314718e-1f);
    p = fmaf(p, f, 1.0f);
    return p * __int_as_float(((int)n + 127) << 23);
}

// ---------------------------------------------------------------------------
// Kernel 0: T5 relative-position bias LUT (exact integer bucket thresholds)
// ---------------------------------------------------------------------------
__global__ void bias_lut_kernel(const float* __restrict__ bias_table) {
    int idx = blockIdx.x * blockDim.x + threadIdx.x;
    if (idx >= H_ * 2 * S_) return;
    int h   = idx >> 12;
    int r   = idx & 4095;
    int rel = r - 2048;
    int bucket = (rel > 0) ? 16 : 0;
    int a = rel < 0 ? -rel : rel;
    int add;
    if      (a <  8) add = a;
    else if (a < 12) add = 8;
    else if (a < 16) add = 9;
    else if (a < 23) add = 10;
    else if (a < 32) add = 11;
    else if (a < 46) add = 12;
    else if (a < 64) add = 13;
    else if (a < 91) add = 14;
    else             add = 15;
    g_bias_lut[idx] = bias_table[(bucket + add) * H_ + h];
}

// ---------------------------------------------------------------------------
// Kernel 1: raw logits = Q K^T / 8 + bias + mask*-1e9 (bf16 3-pass mma) and
// per-(row, kblock) softmax stats (local max, local sumexp).
// Tile 128(q) x 64(k), 8 warps (4x2), warp 32x32, 4 k16-steps (D=64).
// Packed bf16x2 planes, pair-stride 36 (=4 mod 32 -> frag LDS conflict-free).
// ---------------------------------------------------------------------------
#define QSTR 36
__global__ __launch_bounds__(256) void logits_kernel(
    const float* __restrict__ Q, const float* __restrict__ K,
    const int* __restrict__ mask, float* __restrict__ out)
{
    extern __shared__ unsigned smu[];
    unsigned* Qh = smu;                  // [128][36]
    unsigned* Ql = smu + 128 * QSTR;
    unsigned* Kh = smu + 2 * 128 * QSTR; // [64][36]
    unsigned* Kl = Kh + 64 * QSTR;

    int bh = blockIdx.z;
    int q0 = blockIdx.y * 128;
    int k0 = blockIdx.x * 64;
    int b  = bh >> 3;
    int h  = bh & 7;

    const float* Qp = Q + (size_t)bh * S_ * D_;
    const float* Kp = K + (size_t)bh * S_ * D_;

    int t = threadIdx.x;
    int w = t >> 5, l = t & 31, g = l >> 2, tg = l & 3;
    int wm = w & 3, wn = w >> 2;

    // fill Q: 128 rows x 16 float4 = 2048 items
    #pragma unroll
    for (int i = 0; i < 8; i++) {
        int idx = t + i * 256;
        int r = idx >> 4, f4 = idx & 15;
        const float4 qv = *(const float4*)&Qp[(size_t)(q0 + r) * D_ + f4 * 4];
        unsigned h0, l0, h1, l1;
        split_pack(qv.x, qv.y, h0, l0);
        split_pack(qv.z, qv.w, h1, l1);
        Qh[r * QSTR + 2 * f4]     = h0;  Qh[r * QSTR + 2 * f4 + 1] = h1;
        Ql[r * QSTR + 2 * f4]     = l0;  Ql[r * QSTR + 2 * f4 + 1] = l1;
    }
    // fill K: 64 rows x 16 float4 = 1024 items
    #pragma unroll
    for (int i = 0; i < 4; i++) {
        int idx = t + i * 256;
        int r = idx >> 4, f4 = idx & 15;
        const float4 kv = *(const float4*)&Kp[(size_t)(k0 + r) * D_ + f4 * 4];
        unsigned h0, l0, h1, l1;
        split_pack(kv.x, kv.y, h0, l0);
        split_pack(kv.z, kv.w, h1, l1);
        Kh[r * QSTR + 2 * f4]     = h0;  Kh[r * QSTR + 2 * f4 + 1] = h1;
        Kl[r * QSTR + 2 * f4]     = l0;  Kl[r * QSTR + 2 * f4 + 1] = l1;
    }
    __syncthreads();

    float C[2][4][4] = {};

    #pragma unroll
    for (int ks = 0; ks < 4; ks++) {
        int kb = ks * 8;                  // pair offset
        unsigned ah[2][4], al[2][4];
        #pragma unroll
        for (int mt = 0; mt < 2; mt++) {
            int r0 = wm * 32 + mt * 16 + g;
            ah[mt][0] = Qh[r0 * QSTR + kb + tg];
            ah[mt][1] = Qh[(r0 + 8) * QSTR + kb + tg];
            ah[mt][2] = Qh[r0 * QSTR + kb + tg + 4];
            ah[mt][3] = Qh[(r0 + 8) * QSTR + kb + tg + 4];
            al[mt][0] = Ql[r0 * QSTR + kb + tg];
            al[mt][1] = Ql[(r0 + 8) * QSTR + kb + tg];
            al[mt][2] = Ql[r0 * QSTR + kb + tg + 4];
            al[mt][3] = Ql[(r0 + 8) * QSTR + kb + tg + 4];
        }
        unsigned bhf[4][2], blf[4][2];
        #pragma unroll
        for (int nt = 0; nt < 4; nt++) {
            int n = wn * 32 + nt * 8 + g;
            bhf[nt][0] = Kh[n * QSTR + kb + tg];
            bhf[nt][1] = Kh[n * QSTR + kb + tg + 4];
            blf[nt][0] = Kl[n * QSTR + kb + tg];
            blf[nt][1] = Kl[n * QSTR + kb + tg + 4];
        }
        #pragma unroll
        for (int mt = 0; mt < 2; mt++)
            #pragma unroll
            for (int nt = 0; nt < 4; nt++) {
                mma16(C[mt][nt], ah[mt], bhf[nt]);
                mma16(C[mt][nt], ah[mt], blf[nt]);
                mma16(C[mt][nt], al[mt], bhf[nt]);
            }
    }

    // epilogue: finalize logits in C, write raw logits
    float* wbase = out + OUT_OFF + (size_t)bh * S_ * S_;
    const float* lut = g_bias_lut + h * 4096;
    #pragma unroll
    for (int nt = 0; nt < 4; nt++) {
        int kcol = k0 + wn * 32 + nt * 8 + 2 * tg;
        float mv0 = -1e9f * (float)mask[b * S_ + kcol];
        float mv1 = -1e9f * (float)mask[b * S_ + kcol + 1];
        #pragma unroll
        for (int mt = 0; mt < 2; mt++) {
            int q = q0 + wm * 32 + mt * 16 + g;
            C[mt][nt][0] = C[mt][nt][0] * 0.125f + lut[kcol     - q + 2048] + mv0;
            C[mt][nt][1] = C[mt][nt][1] * 0.125f + lut[kcol + 1 - q + 2048] + mv1;
            *(float2*)&wbase[(size_t)q * S_ + kcol] = make_float2(C[mt][nt][0], C[mt][nt][1]);
            int q2 = q + 8;
            C[mt][nt][2] = C[mt][nt][2] * 0.125f + lut[kcol     - q2 + 2048] + mv0;
            C[mt][nt][3] = C[mt][nt][3] * 0.125f + lut[kcol + 1 - q2 + 2048] + mv1;
            *(float2*)&wbase[(size_t)q2 * S_ + kcol] = make_float2(C[mt][nt][2], C[mt][nt][3]);
        }
    }

    // per-row (within this 64-col block) max and sumexp
    float mxv[4], smv[4];
    #pragma unroll
    for (int ri = 0; ri < 4; ri++) {
        int mt = ri >> 1, hf = ri & 1;
        float m = -3.4e38f;
        #pragma unroll
        for (int nt = 0; nt < 4; nt++) {
            m = fmaxf(m, C[mt][nt][hf * 2]);
            m = fmaxf(m, C[mt][nt][hf * 2 + 1]);
        }
        m = fmaxf(m, __shfl_xor_sync(0xffffffffu, m, 1));
        m = fmaxf(m, __shfl_xor_sync(0xffffffffu, m, 2));
        float s = 0.f;
        #pragma unroll
        for (int nt = 0; nt < 4; nt++) {
            s += fast_exp(C[mt][nt][hf * 2]     - m);
            s += fast_exp(C[mt][nt][hf * 2 + 1] - m);
        }
        s += __shfl_xor_sync(0xffffffffu, s, 1);
        s += __shfl_xor_sync(0xffffffffu, s, 2);
        mxv[ri] = m; smv[ri] = s;
    }
    __syncthreads();   // smem reuse barrier

    float* sMax = (float*)smu;          // [128][2]
    float* sSum = sMax + 256;
    if (tg == 0) {
        #pragma unroll
        for (int ri = 0; ri < 4; ri++) {
            int rl = wm * 32 + (ri >> 1) * 16 + (ri & 1) * 8 + g;
            sMax[rl * 2 + wn] = mxv[ri];
            sSum[rl * 2 + wn] = smv[ri];
        }
    }
    __syncthreads();
    if (t < 128) {
        float m0 = sMax[t * 2], m1 = sMax[t * 2 + 1];
        float M = fmaxf(m0, m1);
        float S = sSum[t * 2] * fast_exp(m0 - M) + sSum[t * 2 + 1] * fast_exp(m1 - M);
        g_stats[((size_t)bh * S_ + q0 + t) * KBLK + blockIdx.x] = make_float2(M, S);
    }
}

// ---------------------------------------------------------------------------
// Kernel 2: merge 32 k-block stats per row -> (rowmax, 1/rowsum). 1 warp/row.
// ---------------------------------------------------------------------------
__global__ __launch_bounds__(256) void reduce_kernel()
{
    int t = threadIdx.x;
    int wid = t >> 5, lane = t & 31;
    int row = blockIdx.x * 8 + wid;      // 0 .. BH_*S_-1
    float2 st = g_stats[(size_t)row * KBLK + lane];
    float M = st.x;
    #pragma unroll
    for (int o = 16; o; o >>= 1) M = fmaxf(M, __shfl_xor_sync(0xffffffffu, M, o));
    float S = st.y * fast_exp(st.x - M);
    #pragma unroll
    for (int o = 16; o; o >>= 1) S += __shfl_xor_sync(0xffffffffu, S, o);
    if (lane == 0) g_rowstats[row] = make_float2(M, 1.0f / S);
}

// ---------------------------------------------------------------------------
// Kernel 3: fused softmax-apply + P@V (bf16 3-pass mma).
// Reads raw logits, p = fast_exp(x - M) * invS; writes normalized weights
// back in place; accumulates P@V. Block 64(q) x 64(d), 8 warps, K chunk 64.
// ---------------------------------------------------------------------------
#define PSTR 36
__global__ __launch_bounds__(256) void av_kernel(
    float* __restrict__ W, const float* __restrict__ V, float* __restrict__ out)
{
    extern __shared__ unsigned smu[];
    unsigned* Ph  = smu;                    // [64][36]
    unsigned* Pl  = smu + 64 * PSTR;
    unsigned* Vth = smu + 2 * 64 * PSTR;    // [64(d)][36] (transposed V)
    unsigned* Vtl = Vth + 64 * PSTR;
    float* sM = (float*)(smu + 4 * 64 * PSTR);   // [64]
    float* sI = sM + 64;

    int bh = blockIdx.y;
    int q0 = blockIdx.x * 64;

    float* Wp = W + OUT_OFF + (size_t)bh * S_ * S_;
    const float* Vp = V + (size_t)bh * S_ * D_;

    int t = threadIdx.x;
    int w = t >> 5, l = t & 31, g = l >> 2, tg = l & 3;
    int wm = w & 3, wn = w >> 2;

    if (t < 64) {
        float2 rs = g_rowstats[(size_t)bh * S_ + q0 + t];
        sM[t] = rs.x; sI[t] = rs.y;
    }
    __syncthreads();

    float C[4][4] = {};

    for (int kc = 0; kc < S_; kc += 64) {
        // fill P: read raw logits, softmax-apply, write back, split to bf16
        #pragma unroll
        for (int i = 0; i < 4; i++) {
            int idx = t + i * 256;
            int q = idx >> 4, f4 = idx & 15;
            float* wp = &Wp[(size_t)(q0 + q) * S_ + kc + f4 * 4];
            float4 wv = *(const float4*)wp;
            float M = sM[q], I = sI[q];
            float p0 = fast_exp(wv.x - M) * I;
            float p1 = fast_exp(wv.y - M) * I;
            float p2 = fast_exp(wv.z - M) * I;
            float p3 = fast_exp(wv.w - M) * I;
            *(float4*)wp = make_float4(p0, p1, p2, p3);
            unsigned h0, l0, h1, l1;
            split_pack(p0, p1, h0, l0);
            split_pack(p2, p3, h1, l1);
            Ph[q * PSTR + 2 * f4]     = h0;  Ph[q * PSTR + 2 * f4 + 1] = h1;
            Pl[q * PSTR + 2 * f4]     = l0;  Pl[q * PSTR + 2 * f4 + 1] = l1;
        }
        // fill V transposed: item: kp = pair of k rows, d4 = 4 d-columns
        #pragma unroll
        for (int i = 0; i < 2; i++) {
            int idx = t + i * 256;
            int kp = idx & 31, d4 = idx >> 5;     // d4 0..15
            const float4 va = *(const float4*)&Vp[(size_t)(kc + 2 * kp) * D_ + d4 * 4];
            const float4 vb = *(const float4*)&Vp[(size_t)(kc + 2 * kp + 1) * D_ + d4 * 4];
            unsigned hh, ll;
            split_pack(va.x, vb.x, hh, ll);
            Vth[(4 * d4 + 0) * PSTR + kp] = hh;  Vtl[(4 * d4 + 0) * PSTR + kp] = ll;
            split_pack(va.y, vb.y, hh, ll);
            Vth[(4 * d4 + 1) * PSTR + kp] = hh;  Vtl[(4 * d4 + 1) * PSTR + kp] = ll;
            split_pack(va.z, vb.z, hh, ll);
            Vth[(4 * d4 + 2) * PSTR + kp] = hh;  Vtl[(4 * d4 + 2) * PSTR + kp] = ll;
            split_pack(va.w, vb.w, hh, ll);
            Vth[(4 * d4 + 3) * PSTR + kp] = hh;  Vtl[(4 * d4 + 3) * PSTR + kp] = ll;
        }
        __syncthreads();

        #pragma unroll
        for (int ks = 0; ks < 4; ks++) {
            int kb = ks * 8;
            int r0 = wm * 16 + g;
            unsigned ah[4], al[4];
            ah[0] = Ph[r0 * PSTR + kb + tg];
            ah[1] = Ph[(r0 + 8) * PSTR + kb + tg];
            ah[2] = Ph[r0 * PSTR + kb + tg + 4];
            ah[3] = Ph[(r0 + 8) * PSTR + kb + tg + 4];
            al[0] = Pl[r0 * PSTR + kb + tg];
            al[1] = Pl[(r0 + 8) * PSTR + kb + tg];
            al[2] = Pl[r0 * PSTR + kb + tg + 4];
            al[3] = Pl[(r0 + 8) * PSTR + kb + tg + 4];
            #pragma unroll
            for (int nt = 0; nt < 4; nt++) {
                int n = wn * 32 + nt * 8 + g;
                unsigned bhf[2], blf[2];
                bhf[0] = Vth[n * PSTR + kb + tg];
                bhf[1] = Vth[n * PSTR + kb + tg + 4];
                blf[0] = Vtl[n * PSTR + kb + tg];
                blf[1] = Vtl[n * PSTR + kb + tg + 4];
                mma16(C[nt], ah, bhf);
                mma16(C[nt], ah, blf);
                mma16(C[nt], al, bhf);
            }
        }
        __syncthreads();
    }

    #pragma unroll
    for (int nt = 0; nt < 4; nt++) {
        int d = wn * 32 + nt * 8 + 2 * tg;
        int q = q0 + wm * 16 + g;
        *(float2*)&out[((size_t)bh * S_ + q) * D_ + d]     = make_float2(C[nt][0], C[nt][1]);
        *(float2*)&out[((size_t)bh * S_ + q + 8) * D_ + d] = make_float2(C[nt][2], C[nt][3]);
    }
}

// ---------------------------------------------------------------------------
extern "C" void kernel_launch(void* const* d_in, const int* in_sizes, int n_in,
                              void* d_out, int out_size)
{
    const float* Q    = (const float*)d_in[0];
    const float* K    = (const float*)d_in[1];
    const float* V    = (const float*)d_in[2];
    const int*   mask = (const int*)d_in[3];
    const float* bt   = (const float*)d_in[4];
    float* out = (float*)d_out;

    const int logits_smem = (2 * 128 * QSTR + 2 * 64 * QSTR) * 4;   // 55296
    const int av_smem     = (4 * 64 * PSTR + 128) * 4;              // 37376
    cudaFuncSetAttribute(logits_kernel, cudaFuncAttributeMaxDynamicSharedMemorySize, logits_smem);
    cudaFuncSetAttribute(av_kernel,     cudaFuncAttributeMaxDynamicSharedMemorySize, av_smem);

    bias_lut_kernel<<<32, 1024>>>(bt);

    dim3 g1(S_ / 64, S_ / 128, BH_);    // (32, 16, 16)
    logits_kernel<<<g1, 256, logits_smem>>>(Q, K, mask, out);

    reduce_kernel<<<BH_ * S_ / 8, 256>>>();

    dim3 g2(S_ / 64, BH_);              // (32, 16)
    av_kernel<<<g2, 256, av_smem>>>(out, V, out);
}

// round 7
// speedup vs baseline: 1.7425x; 1.1307x over previous
#include <cuda_runtime.h>
#include <cuda_bf16.h>
#include <cstdint>

#define B_ 2
#define H_ 8
#define S_ 2048
#define D_ 64
#define BH_ (B_ * H_)
#define OUT_OFF ((size_t)B_ * H_ * S_ * D_)   // output tensor first, then weights
#define KBLK 32                                // 2048/64 k-blocks per row

__device__ float  g_bias_lut[H_ * 2 * S_];            // 8 * 4096
__device__ float2 g_stats[BH_ * S_ * KBLK];           // per (row, kblock): (max, sumexp)
__device__ float2 g_rowstats[BH_ * S_];               // per row: (max, 1/sum)
// packed transposed V planes: [bh][chunk][d=64][kp=32]
__device__ unsigned g_Vth[BH_ * KBLK * 64 * 32];      // 4MB
__device__ unsigned g_Vtl[BH_ * KBLK * 64 * 32];      // 4MB

// ---- bf16 split/pack helpers ------------------------------------------------
__device__ __forceinline__ void split_pack(float x0, float x1, unsigned& hi, unsigned& lo) {
    __nv_bfloat162 h = __floats2bfloat162_rn(x0, x1);
    float f0 = __bfloat162float(__low2bfloat16(h));
    float f1 = __bfloat162float(__high2bfloat16(h));
    __nv_bfloat162 l = __floats2bfloat162_rn(x0 - f0, x1 - f1);
    hi = *reinterpret_cast<unsigned*>(&h);
    lo = *reinterpret_cast<unsigned*>(&l);
}
__device__ __forceinline__ void mma16(float* d, const unsigned* a, const unsigned* b) {
    asm("mma.sync.aligned.m16n8k16.row.col.f32.bf16.bf16.f32 "
        "{%0,%1,%2,%3},{%4,%5,%6,%7},{%8,%9},{%0,%1,%2,%3};"
        : "+f"(d[0]), "+f"(d[1]), "+f"(d[2]), "+f"(d[3])
        : "r"(a[0]), "r"(a[1]), "r"(a[2]), "r"(a[3]), "r"(b[0]), "r"(b[1]));
}
__device__ __forceinline__ void cpa16(unsigned dst, const void* src) {
    asm volatile("cp.async.cg.shared.global [%0], [%1], 16;" :: "r"(dst), "l"(src));
}
__device__ __forceinline__ void cpa_commit() {
    asm volatile("cp.async.commit_group;");
}
__device__ __forceinline__ void cpa_wait0() {
    asm volatile("cp.async.wait_group 0;");
}

// fast exp (FMA pipe only), valid for x <= 0, underflow clamp
__device__ __forceinline__ float fast_exp(float x) {
    x = fmaxf(x, -87.0f);
    float y = x * 1.4426950408889634f;
    float n = rintf(y);
    float f = y - n;
    float p = 1.5403530e-4f;
    p = fmaf(p, f, 1.3333558e-3f);
    p = fmaf(p, f, 9.6181291e-3f);
    p = fmaf(p, f, 5.5504109e-2f);
    p = fmaf(p, f, 2.4022651e-1f);
    p = fmaf(p, f, 6.9314718e-1f);
    p = fmaf(p, f, 1.0f);
    return p * __int_as_float(((int)n + 127) << 23);
}

// ---------------------------------------------------------------------------
// Kernel 0: T5 relative-position bias LUT (exact integer bucket thresholds)
// ---------------------------------------------------------------------------
__global__ void bias_lut_kernel(const float* __restrict__ bias_table) {
    int idx = blockIdx.x * blockDim.x + threadIdx.x;
    if (idx >= H_ * 2 * S_) return;
    int h   = idx >> 12;
    int r   = idx & 4095;
    int rel = r - 2048;
    int bucket = (rel > 0) ? 16 : 0;
    int a = rel < 0 ? -rel : rel;
    int add;
    if      (a <  8) add = a;
    else if (a < 12) add = 8;
    else if (a < 16) add = 9;
    else if (a < 23) add = 10;
    else if (a < 32) add = 11;
    else if (a < 46) add = 12;
    else if (a < 64) add = 13;
    else if (a < 91) add = 14;
    else             add = 15;
    g_bias_lut[idx] = bias_table[(bucket + add) * H_ + h];
}

// ---------------------------------------------------------------------------
// Kernel 0b: V -> packed transposed bf16 hi/lo planes [bh][chunk][d][kp]
// ---------------------------------------------------------------------------
__global__ __launch_bounds__(256) void v_prep_kernel(const float* __restrict__ V)
{
    __shared__ float Vs[64 * 68];     // [k][d] raw tile
    int c  = blockIdx.x;              // chunk
    int bh = blockIdx.y;
    int t  = threadIdx.x;
    const float* Vp = V + (size_t)bh * S_ * D_ + (size_t)c * 64 * D_;
    #pragma unroll
    for (int i = 0; i < 4; i++) {
        int idx = t + i * 256;
        int k = idx >> 4, d4 = idx & 15;
        *(float4*)&Vs[k * 68 + d4 * 4] = *(const float4*)&Vp[(size_t)k * D_ + d4 * 4];
    }
    __syncthreads();
    unsigned base = ((unsigned)bh * KBLK + c) * 64 * 32;
    #pragma unroll
    for (int i = 0; i < 8; i++) {
        int idx = t + i * 256;
        int d = idx >> 5, kp = idx & 31;
        float va = Vs[(2 * kp) * 68 + d];
        float vb = Vs[(2 * kp + 1) * 68 + d];
        unsigned hh, ll;
        split_pack(va, vb, hh, ll);
        g_Vth[base + d * 32 + kp] = hh;
        g_Vtl[base + d * 32 + kp] = ll;
    }
}

// ---------------------------------------------------------------------------
// Kernel 1: raw logits = Q K^T / 8 + bias + mask*-1e9 (bf16 3-pass mma) and
// per-(row, kblock) softmax stats. Tile 128(q) x 64(k), 8 warps (4x2).
// ---------------------------------------------------------------------------
#define QSTR 36
__global__ __launch_bounds__(256) void logits_kernel(
    const float* __restrict__ Q, const float* __restrict__ K,
    const int* __restrict__ mask, float* __restrict__ out)
{
    extern __shared__ unsigned smu[];
    unsigned* Qh = smu;                  // [128][36]
    unsigned* Ql = smu + 128 * QSTR;
    unsigned* Kh = smu + 2 * 128 * QSTR; // [64][36]
    unsigned* Kl = Kh + 64 * QSTR;
    float* sLut  = (float*)(Kl + 64 * QSTR);   // [192]

    int bh = blockIdx.z;
    int q0 = blockIdx.y * 128;
    int k0 = blockIdx.x * 64;
    int b  = bh >> 3;
    int h  = bh & 7;

    const float* Qp = Q + (size_t)bh * S_ * D_;
    const float* Kp = K + (size_t)bh * S_ * D_;

    int t = threadIdx.x;
    int w = t >> 5, l = t & 31, g = l >> 2, tg = l & 3;
    int wm = w & 3, wn = w >> 2;

    // LUT window: lut[base + j], j = (kcol-k0) - (q-q0) + 128 in [1,191]
    int lbase = k0 - q0 + 2048 - 128;
    if (t < 192) {
        int ix = lbase + t;
        ix = ix < 0 ? 0 : (ix > 4095 ? 4095 : ix);
        sLut[t] = g_bias_lut[h * 4096 + ix];
    }

    // fill Q: 128 rows x 16 float4
    #pragma unroll
    for (int i = 0; i < 8; i++) {
        int idx = t + i * 256;
        int r = idx >> 4, f4 = idx & 15;
        const float4 qv = *(const float4*)&Qp[(size_t)(q0 + r) * D_ + f4 * 4];
        unsigned h0, l0, h1, l1;
        split_pack(qv.x, qv.y, h0, l0);
        split_pack(qv.z, qv.w, h1, l1);
        Qh[r * QSTR + 2 * f4]     = h0;  Qh[r * QSTR + 2 * f4 + 1] = h1;
        Ql[r * QSTR + 2 * f4]     = l0;  Ql[r * QSTR + 2 * f4 + 1] = l1;
    }
    // fill K: 64 rows x 16 float4
    #pragma unroll
    for (int i = 0; i < 4; i++) {
        int idx = t + i * 256;
        int r = idx >> 4, f4 = idx & 15;
        const float4 kv = *(const float4*)&Kp[(size_t)(k0 + r) * D_ + f4 * 4];
        unsigned h0, l0, h1, l1;
        split_pack(kv.x, kv.y, h0, l0);
        split_pack(kv.z, kv.w, h1, l1);
        Kh[r * QSTR + 2 * f4]     = h0;  Kh[r * QSTR + 2 * f4 + 1] = h1;
        Kl[r * QSTR + 2 * f4]     = l0;  Kl[r * QSTR + 2 * f4 + 1] = l1;
    }
    __syncthreads();

    float C[2][4][4] = {};

    #pragma unroll
    for (int ks = 0; ks < 4; ks++) {
        int kb = ks * 8;
        unsigned ah[2][4], al[2][4];
        #pragma unroll
        for (int mt = 0; mt < 2; mt++) {
            int r0 = wm * 32 + mt * 16 + g;
            ah[mt][0] = Qh[r0 * QSTR + kb + tg];
            ah[mt][1] = Qh[(r0 + 8) * QSTR + kb + tg];
            ah[mt][2] = Qh[r0 * QSTR + kb + tg + 4];
            ah[mt][3] = Qh[(r0 + 8) * QSTR + kb + tg + 4];
            al[mt][0] = Ql[r0 * QSTR + kb + tg];
            al[mt][1] = Ql[(r0 + 8) * QSTR + kb + tg];
            al[mt][2] = Ql[r0 * QSTR + kb + tg + 4];
            al[mt][3] = Ql[(r0 + 8) * QSTR + kb + tg + 4];
        }
        unsigned bhf[4][2], blf[4][2];
        #pragma unroll
        for (int nt = 0; nt < 4; nt++) {
            int n = wn * 32 + nt * 8 + g;
            bhf[nt][0] = Kh[n * QSTR + kb + tg];
            bhf[nt][1] = Kh[n * QSTR + kb + tg + 4];
            blf[nt][0] = Kl[n * QSTR + kb + tg];
            blf[nt][1] = Kl[n * QSTR + kb + tg + 4];
        }
        #pragma unroll
        for (int mt = 0; mt < 2; mt++)
            #pragma unroll
            for (int nt = 0; nt < 4; nt++) {
                mma16(C[mt][nt], ah[mt], bhf[nt]);
                mma16(C[mt][nt], ah[mt], blf[nt]);
                mma16(C[mt][nt], al[mt], bhf[nt]);
            }
    }

    // epilogue: finalize logits, write raw
    float* wbase = out + OUT_OFF + (size_t)bh * S_ * S_;
    #pragma unroll
    for (int nt = 0; nt < 4; nt++) {
        int kcol = k0 + wn * 32 + nt * 8 + 2 * tg;
        int jc = (kcol - k0) + 128;
        float mv0 = -1e9f * (float)mask[b * S_ + kcol];
        float mv1 = -1e9f * (float)mask[b * S_ + kcol + 1];
        #pragma unroll
        for (int mt = 0; mt < 2; mt++) {
            int q = q0 + wm * 32 + mt * 16 + g;
            int jq = jc - (q - q0);
            C[mt][nt][0] = C[mt][nt][0] * 0.125f + sLut[jq]     + mv0;
            C[mt][nt][1] = C[mt][nt][1] * 0.125f + sLut[jq + 1] + mv1;
            *(float2*)&wbase[(size_t)q * S_ + kcol] = make_float2(C[mt][nt][0], C[mt][nt][1]);
            int jq2 = jq - 8;
            C[mt][nt][2] = C[mt][nt][2] * 0.125f + sLut[jq2]     + mv0;
            C[mt][nt][3] = C[mt][nt][3] * 0.125f + sLut[jq2 + 1] + mv1;
            *(float2*)&wbase[(size_t)(q + 8) * S_ + kcol] = make_float2(C[mt][nt][2], C[mt][nt][3]);
        }
    }

    // per-row (64-col block) max & sumexp
    float mxv[4], smv[4];
    #pragma unroll
    for (int ri = 0; ri < 4; ri++) {
        int mt = ri >> 1, hf = ri & 1;
        float m = -3.4e38f;
        #pragma unroll
        for (int nt = 0; nt < 4; nt++) {
            m = fmaxf(m, C[mt][nt][hf * 2]);
            m = fmaxf(m, C[mt][nt][hf * 2 + 1]);
        }
        m = fmaxf(m, __shfl_xor_sync(0xffffffffu, m, 1));
        m = fmaxf(m, __shfl_xor_sync(0xffffffffu, m, 2));
        float s = 0.f;
        #pragma unroll
        for (int nt = 0; nt < 4; nt++) {
            s += fast_exp(C[mt][nt][hf * 2]     - m);
            s += fast_exp(C[mt][nt][hf * 2 + 1] - m);
        }
        s += __shfl_xor_sync(0xffffffffu, s, 1);
        s += __shfl_xor_sync(0xffffffffu, s, 2);
        mxv[ri] = m; smv[ri] = s;
    }
    __syncthreads();

    float* sMax = (float*)smu;          // [128][2]
    float* sSum = sMax + 256;
    if (tg == 0) {
        #pragma unroll
        for (int ri = 0; ri < 4; ri++) {
            int rl = wm * 32 + (ri >> 1) * 16 + (ri & 1) * 8 + g;
            sMax[rl * 2 + wn] = mxv[ri];
            sSum[rl * 2 + wn] = smv[ri];
        }
    }
    __syncthreads();
    if (t < 128) {
        float m0 = sMax[t * 2], m1 = sMax[t * 2 + 1];
        float M = fmaxf(m0, m1);
        float Sv = sSum[t * 2] * fast_exp(m0 - M) + sSum[t * 2 + 1] * fast_exp(m1 - M);
        g_stats[((size_t)bh * S_ + q0 + t) * KBLK + blockIdx.x] = make_float2(M, Sv);
    }
}

// ---------------------------------------------------------------------------
// Kernel 2: merge k-block stats per row -> (rowmax, 1/rowsum). 1 warp/row.
// ---------------------------------------------------------------------------
__global__ __launch_bounds__(256) void reduce_kernel()
{
    int t = threadIdx.x;
    int wid = t >> 5, lane = t & 31;
    int row = blockIdx.x * 8 + wid;
    float2 st = g_stats[(size_t)row * KBLK + lane];
    float M = st.x;
    #pragma unroll
    for (int o = 16; o; o >>= 1) M = fmaxf(M, __shfl_xor_sync(0xffffffffu, M, o));
    float Sv = st.y * fast_exp(st.x - M);
    #pragma unroll
    for (int o = 16; o; o >>= 1) Sv += __shfl_xor_sync(0xffffffffu, Sv, o);
    if (lane == 0) g_rowstats[row] = make_float2(M, 1.0f / Sv);
}

// ---------------------------------------------------------------------------
// Kernel 3: fused softmax-apply + P@V, cp.async double-buffered.
// Block 64(q) x 64(d), 8 warps (4x2), K chunk 64.
// smem (floats): rawW[2][64][68] | Ph[64][36] Pl[64][36] | Vh[2][64][36]
//                Vl[2][64][36] | sM[64] sI[64]
// ---------------------------------------------------------------------------
#define PSTR 36
#define RAWSTR 68
#define OFF_RAW   0
#define OFF_PH    (2 * 64 * RAWSTR)                 // 8704
#define OFF_PL    (OFF_PH + 64 * PSTR)              // 11008
#define OFF_VH    (OFF_PL + 64 * PSTR)              // 13312
#define OFF_VL    (OFF_VH + 2 * 64 * PSTR)          // 17920
#define OFF_ST    (OFF_VL + 2 * 64 * PSTR)          // 22528
#define AV_SMEM   ((OFF_ST + 128) * 4)              // 90624 B

__global__ __launch_bounds__(256) void av_kernel(
    float* __restrict__ W, const float* __restrict__ V, float* __restrict__ out)
{
    extern __shared__ unsigned smu[];
    float*    rawW = (float*)smu;
    unsigned* Ph   = smu + OFF_PH;
    unsigned* Pl   = smu + OFF_PL;
    unsigned* Vh   = smu + OFF_VH;
    unsigned* Vl   = smu + OFF_VL;
    float*    sM   = (float*)(smu + OFF_ST);
    float*    sI   = sM + 64;

    int bh = blockIdx.y;
    int q0 = blockIdx.x * 64;

    float* Wp = W + OUT_OFF + (size_t)bh * S_ * S_;

    int t = threadIdx.x;
    int w = t >> 5, l = t & 31, g = l >> 2, tg = l & 3;
    int wm = w & 3, wn = w >> 2;

    unsigned sbase = (unsigned)__cvta_generic_to_shared(smu);

    if (t < 64) {
        float2 rs = g_rowstats[(size_t)bh * S_ + q0 + t];
        sM[t] = rs.x; sI[t] = rs.y;
    }

    // prefetch chunk 0 into stage 0
    {
        int s = 0;
        #pragma unroll
        for (int i = 0; i < 4; i++) {
            int idx = t + i * 256;
            int r = idx >> 4, c4 = idx & 15;
            cpa16(sbase + (OFF_RAW + s * 64 * RAWSTR + r * RAWSTR + c4 * 4) * 4,
                  &Wp[(size_t)(q0 + r) * S_ + c4 * 4]);
        }
        unsigned vb = ((unsigned)bh * KBLK + 0) * 64 * 32;
        #pragma unroll
        for (int i = 0; i < 2; i++) {
            int idx = t + i * 256;
            int d = idx >> 3, sg = idx & 7;
            cpa16(sbase + (OFF_VH + s * 64 * PSTR + d * PSTR + sg * 4) * 4,
                  &g_Vth[vb + d * 32 + sg * 4]);
            cpa16(sbase + (OFF_VL + s * 64 * PSTR + d * PSTR + sg * 4) * 4,
                  &g_Vtl[vb + d * 32 + sg * 4]);
        }
        cpa_commit();
    }

    float C[4][4] = {};

    for (int kci = 0; kci < KBLK; kci++) {
        int kc = kci * 64;
        int st = kci & 1;
        cpa_wait0();
        __syncthreads();

        // prefetch next chunk
        if (kci + 1 < KBLK) {
            int s = (kci + 1) & 1;
            #pragma unroll
            for (int i = 0; i < 4; i++) {
                int idx = t + i * 256;
                int r = idx >> 4, c4 = idx & 15;
                cpa16(sbase + (OFF_RAW + s * 64 * RAWSTR + r * RAWSTR + c4 * 4) * 4,
                      &Wp[(size_t)(q0 + r) * S_ + kc + 64 + c4 * 4]);
            }
            unsigned vb = ((unsigned)bh * KBLK + kci + 1) * 64 * 32;
            #pragma unroll
            for (int i = 0; i < 2; i++) {
                int idx = t + i * 256;
                int d = idx >> 3, sg = idx & 7;
                cpa16(sbase + (OFF_VH + s * 64 * PSTR + d * PSTR + sg * 4) * 4,
                      &g_Vth[vb + d * 32 + sg * 4]);
                cpa16(sbase + (OFF_VL + s * 64 * PSTR + d * PSTR + sg * 4) * 4,
                      &g_Vtl[vb + d * 32 + sg * 4]);
            }
            cpa_commit();
        }

        // fill P: raw from smem, softmax-apply, write back, pack
        #pragma unroll
        for (int i = 0; i < 4; i++) {
            int idx = t + i * 256;
            int q = idx >> 4, f4 = idx & 15;
            float4 wv = *(const float4*)&rawW[st * 64 * RAWSTR + q * RAWSTR + f4 * 4];
            float M = sM[q], I = sI[q];
            float p0 = fast_exp(wv.x - M) * I;
            float p1 = fast_exp(wv.y - M) * I;
            float p2 = fast_exp(wv.z - M) * I;
            float p3 = fast_exp(wv.w - M) * I;
            *(float4*)&Wp[(size_t)(q0 + q) * S_ + kc + f4 * 4] = make_float4(p0, p1, p2, p3);
            unsigned h0, l0, h1, l1;
            split_pack(p0, p1, h0, l0);
            split_pack(p2, p3, h1, l1);
            *(uint2*)&Ph[q * PSTR + 2 * f4] = make_uint2(h0, h1);
            *(uint2*)&Pl[q * PSTR + 2 * f4] = make_uint2(l0, l1);
        }
        __syncthreads();

        unsigned* Vth = Vh + st * 64 * PSTR;
        unsigned* Vtl = Vl + st * 64 * PSTR;
        #pragma unroll
        for (int ks = 0; ks < 4; ks++) {
            int kb = ks * 8;
            int r0 = wm * 16 + g;
            unsigned ah[4], al[4];
            ah[0] = Ph[r0 * PSTR + kb + tg];
            ah[1] = Ph[(r0 + 8) * PSTR + kb + tg];
            ah[2] = Ph[r0 * PSTR + kb + tg + 4];
            ah[3] = Ph[(r0 + 8) * PSTR + kb + tg + 4];
            al[0] = Pl[r0 * PSTR + kb + tg];
            al[1] = Pl[(r0 + 8) * PSTR + kb + tg];
            al[2] = Pl[r0 * PSTR + kb + tg + 4];
            al[3] = Pl[(r0 + 8) * PSTR + kb + tg + 4];
            #pragma unroll
            for (int nt = 0; nt < 4; nt++) {
                int n = wn * 32 + nt * 8 + g;
                unsigned bhf[2], blf[2];
                bhf[0] = Vth[n * PSTR + kb + tg];
                bhf[1] = Vth[n * PSTR + kb + tg + 4];
                blf[0] = Vtl[n * PSTR + kb + tg];
                blf[1] = Vtl[n * PSTR + kb + tg + 4];
                mma16(C[nt], ah, bhf);
                mma16(C[nt], ah, blf);
                mma16(C[nt], al, bhf);
            }
        }
        __syncthreads();
    }

    #pragma unroll
    for (int nt = 0; nt < 4; nt++) {
        int d = wn * 32 + nt * 8 + 2 * tg;
        int q = q0 + wm * 16 + g;
        *(float2*)&out[((size_t)bh * S_ + q) * D_ + d]     = make_float2(C[nt][0], C[nt][1]);
        *(float2*)&out[((size_t)bh * S_ + q + 8) * D_ + d] = make_float2(C[nt][2], C[nt][3]);
    }
}

// ---------------------------------------------------------------------------
extern "C" void kernel_launch(void* const* d_in, const int* in_sizes, int n_in,
                              void* d_out, int out_size)
{
    const float* Q    = (const float*)d_in[0];
    const float* K    = (const float*)d_in[1];
    const float* V    = (const float*)d_in[2];
    const int*   mask = (const int*)d_in[3];
    const float* bt   = (const float*)d_in[4];
    float* out = (float*)d_out;

    const int logits_smem = (2 * 128 * QSTR + 2 * 64 * QSTR + 192) * 4;   // 56064
    cudaFuncSetAttribute(logits_kernel, cudaFuncAttributeMaxDynamicSharedMemorySize, logits_smem);
    cudaFuncSetAttribute(av_kernel,     cudaFuncAttributeMaxDynamicSharedMemorySize, AV_SMEM);

    bias_lut_kernel<<<32, 1024>>>(bt);

    dim3 gv(KBLK, BH_);
    v_prep_kernel<<<gv, 256>>>(V);

    dim3 g1(S_ / 64, S_ / 128, BH_);    // (32, 16, 16)
    logits_kernel<<<g1, 256, logits_smem>>>(Q, K, mask, out);

    reduce_kernel<<<BH_ * S_ / 8, 256>>>();

    dim3 g2(S_ / 64, BH_);              // (32, 16)
    av_kernel<<<g2, 256, AV_SMEM>>>(out, V, out);
}

// round 8
// speedup vs baseline: 2.0221x; 1.1605x over previous
#include <cuda_runtime.h>
#include <cuda_bf16.h>
#include <cstdint>

#define B_ 2
#define H_ 8
#define S_ 2048
#define D_ 64
#define BH_ (B_ * H_)
#define OUT_OFF ((size_t)B_ * H_ * S_ * D_)   // output tensor first, then weights
#define KBLK 32                                // av: 2048/64 chunks
#define QBLK 16                                // logits: 2048/128 k-blocks

__device__ float  g_bias_lut[H_ * 2 * S_];            // 8 * 4096
__device__ float2 g_stats[BH_ * S_ * QBLK];           // per (row, 128-kblock): (max, sumexp)
__device__ float2 g_rowstats[BH_ * S_];               // per row: (max, 1/sum)
// packed transposed V planes: [bh][chunk][d=64][kp=32]
__device__ unsigned g_Vth[BH_ * KBLK * 64 * 32];
__device__ unsigned g_Vtl[BH_ * KBLK * 64 * 32];

// ---- helpers ----------------------------------------------------------------
__device__ __forceinline__ void split_pack(float x0, float x1, unsigned& hi, unsigned& lo) {
    __nv_bfloat162 h = __floats2bfloat162_rn(x0, x1);
    float f0 = __bfloat162float(__low2bfloat16(h));
    float f1 = __bfloat162float(__high2bfloat16(h));
    __nv_bfloat162 l = __floats2bfloat162_rn(x0 - f0, x1 - f1);
    hi = *reinterpret_cast<unsigned*>(&h);
    lo = *reinterpret_cast<unsigned*>(&l);
}
__device__ __forceinline__ void mma16(float* d, const unsigned* a, const unsigned* b) {
    asm("mma.sync.aligned.m16n8k16.row.col.f32.bf16.bf16.f32 "
        "{%0,%1,%2,%3},{%4,%5,%6,%7},{%8,%9},{%0,%1,%2,%3};"
        : "+f"(d[0]), "+f"(d[1]), "+f"(d[2]), "+f"(d[3])
        : "r"(a[0]), "r"(a[1]), "r"(a[2]), "r"(a[3]), "r"(b[0]), "r"(b[1]));
}
__device__ __forceinline__ void ldm4(unsigned* r, unsigned addr) {
    asm volatile("ldmatrix.sync.aligned.m8n8.x4.shared.b16 {%0,%1,%2,%3}, [%4];"
        : "=r"(r[0]), "=r"(r[1]), "=r"(r[2]), "=r"(r[3]) : "r"(addr));
}
__device__ __forceinline__ void cpa16(unsigned dst, const void* src) {
    asm volatile("cp.async.cg.shared.global [%0], [%1], 16;" :: "r"(dst), "l"(src));
}
__device__ __forceinline__ void cpa_commit() { asm volatile("cp.async.commit_group;"); }
__device__ __forceinline__ void cpa_wait0()  { asm volatile("cp.async.wait_group 0;"); }

__device__ __forceinline__ float ex2f(float x) {
    float r; asm("ex2.approx.f32 %0, %1;" : "=f"(r) : "f"(x)); return r;
}
#define LOG2E 1.4426950408889634f
__device__ __forceinline__ float fast_exp(float x) { return ex2f(x * LOG2E); }

// ---------------------------------------------------------------------------
// Kernel 0: T5 relative-position bias LUT (exact integer bucket thresholds)
// ---------------------------------------------------------------------------
__global__ void bias_lut_kernel(const float* __restrict__ bias_table) {
    int idx = blockIdx.x * blockDim.x + threadIdx.x;
    if (idx >= H_ * 2 * S_) return;
    int h   = idx >> 12;
    int r   = idx & 4095;
    int rel = r - 2048;
    int bucket = (rel > 0) ? 16 : 0;
    int a = rel < 0 ? -rel : rel;
    int add;
    if      (a <  8) add = a;
    else if (a < 12) add = 8;
    else if (a < 16) add = 9;
    else if (a < 23) add = 10;
    else if (a < 32) add = 11;
    else if (a < 46) add = 12;
    else if (a < 64) add = 13;
    else if (a < 91) add = 14;
    else             add = 15;
    g_bias_lut[idx] = bias_table[(bucket + add) * H_ + h];
}

// ---------------------------------------------------------------------------
// Kernel 0b: V -> packed transposed bf16 hi/lo planes [bh][chunk][d][kp]
// ---------------------------------------------------------------------------
__global__ __launch_bounds__(256) void v_prep_kernel(const float* __restrict__ V)
{
    __shared__ float Vs[64 * 68];
    int c  = blockIdx.x;
    int bh = blockIdx.y;
    int t  = threadIdx.x;
    const float* Vp = V + (size_t)bh * S_ * D_ + (size_t)c * 64 * D_;
    #pragma unroll
    for (int i = 0; i < 4; i++) {
        int idx = t + i * 256;
        int k = idx >> 4, d4 = idx & 15;
        *(float4*)&Vs[k * 68 + d4 * 4] = *(const float4*)&Vp[(size_t)k * D_ + d4 * 4];
    }
    __syncthreads();
    unsigned base = ((unsigned)bh * KBLK + c) * 64 * 32;
    #pragma unroll
    for (int i = 0; i < 8; i++) {
        int idx = t + i * 256;
        int d = idx >> 5, kp = idx & 31;
        float va = Vs[(2 * kp) * 68 + d];
        float vb = Vs[(2 * kp + 1) * 68 + d];
        unsigned hh, ll;
        split_pack(va, vb, hh, ll);
        g_Vth[base + d * 32 + kp] = hh;
        g_Vtl[base + d * 32 + kp] = ll;
    }
}

// ---------------------------------------------------------------------------
// Kernel 1: raw logits (bf16 3-pass mma) + per-(row,128-kblock) stats.
// Tile 128(q) x 128(k), 8 warps (4m x 2n), warp tile 32 x 64.
// ---------------------------------------------------------------------------
#define QSTR 36
#define L_QH 0
#define L_QL (128 * QSTR)
#define L_KH (2 * 128 * QSTR)
#define L_KL (3 * 128 * QSTR)
#define L_LUT (4 * 128 * QSTR)
#define L_SMEM ((L_LUT + 288) * 4)

__global__ __launch_bounds__(256, 2) void logits_kernel(
    const float* __restrict__ Q, const float* __restrict__ K,
    const int* __restrict__ mask, float* __restrict__ out)
{
    extern __shared__ unsigned smu[];
    unsigned* Qh = smu + L_QH;
    unsigned* Ql = smu + L_QL;
    unsigned* Kh = smu + L_KH;
    unsigned* Kl = smu + L_KL;
    float* sLut  = (float*)(smu + L_LUT);

    int bh = blockIdx.z;
    int q0 = blockIdx.y * 128;
    int k0 = blockIdx.x * 128;
    int b  = bh >> 3;
    int h  = bh & 7;

    const float* Qp = Q + (size_t)bh * S_ * D_;
    const float* Kp = K + (size_t)bh * S_ * D_;

    int t = threadIdx.x;
    int w = t >> 5, l = t & 31, g = l >> 2, tg = l & 3;
    int wm = w & 3, wn = w >> 2;

    // LUT window: j = (kcol-k0) - (q-q0) + 128 in [1,255]
    int lbase = k0 - q0 + 2048 - 128;
    for (int i = t; i < 288; i += 256) {
        int ix = lbase + i;
        ix = ix < 0 ? 0 : (ix > 4095 ? 4095 : ix);
        sLut[i] = g_bias_lut[h * 4096 + ix];
    }

    // fill Q and K: 128 rows x 16 float4 each
    #pragma unroll
    for (int i = 0; i < 8; i++) {
        int idx = t + i * 256;
        int r = idx >> 4, f4 = idx & 15;
        const float4 qv = *(const float4*)&Qp[(size_t)(q0 + r) * D_ + f4 * 4];
        unsigned h0, l0, h1, l1;
        split_pack(qv.x, qv.y, h0, l0);
        split_pack(qv.z, qv.w, h1, l1);
        *(uint2*)&Qh[r * QSTR + 2 * f4] = make_uint2(h0, h1);
        *(uint2*)&Ql[r * QSTR + 2 * f4] = make_uint2(l0, l1);
        const float4 kv = *(const float4*)&Kp[(size_t)(k0 + r) * D_ + f4 * 4];
        split_pack(kv.x, kv.y, h0, l0);
        split_pack(kv.z, kv.w, h1, l1);
        *(uint2*)&Kh[r * QSTR + 2 * f4] = make_uint2(h0, h1);
        *(uint2*)&Kl[r * QSTR + 2 * f4] = make_uint2(l0, l1);
    }
    __syncthreads();

    unsigned sbase = (unsigned)__cvta_generic_to_shared(smu);
    // ldmatrix lane address components
    int lq = l & 7, lh8 = (l >> 3) & 1, lc = (l >> 4);          // A: x4 quads
    int qd = l >> 3;                                            // B: quad id
    unsigned aoff = ((wm * 32 + lh8 * 8 + lq) * QSTR + lc * 4) * 4;
    unsigned boff = ((wn * 64 + (qd >> 1) * 8 + lq) * QSTR + (qd & 1) * 4) * 4;

    float C[2][8][4] = {};

    #pragma unroll
    for (int ks = 0; ks < 4; ks++) {
        unsigned ah[2][4], al[2][4];
        #pragma unroll
        for (int mt = 0; mt < 2; mt++) {
            ldm4(ah[mt], sbase + L_QH * 4 + aoff + mt * (16 * QSTR * 4) + ks * 32);
            ldm4(al[mt], sbase + L_QL * 4 + aoff + mt * (16 * QSTR * 4) + ks * 32);
        }
        #pragma unroll
        for (int ntp = 0; ntp < 4; ntp++) {
            unsigned bhf[4], blf[4];   // [b0,b1] for nt=2*ntp, then nt=2*ntp+1
            ldm4(bhf, sbase + L_KH * 4 + boff + ntp * (16 * QSTR * 4) + ks * 32);
            ldm4(blf, sbase + L_KL * 4 + boff + ntp * (16 * QSTR * 4) + ks * 32);
            #pragma unroll
            for (int mt = 0; mt < 2; mt++) {
                mma16(C[mt][2 * ntp],     ah[mt], bhf);
                mma16(C[mt][2 * ntp],     ah[mt], blf);
                mma16(C[mt][2 * ntp],     al[mt], bhf);
                mma16(C[mt][2 * ntp + 1], ah[mt], bhf + 2);
                mma16(C[mt][2 * ntp + 1], ah[mt], blf + 2);
                mma16(C[mt][2 * ntp + 1], al[mt], bhf + 2);
            }
        }
    }

    // epilogue: finalize logits, write raw
    float* wbase = out + OUT_OFF + (size_t)bh * S_ * S_;
    #pragma unroll
    for (int nt = 0; nt < 8; nt++) {
        int kcol = k0 + wn * 64 + nt * 8 + 2 * tg;
        int jc = (kcol - k0) + 128;
        float mv0 = -1e9f * (float)mask[b * S_ + kcol];
        float mv1 = -1e9f * (float)mask[b * S_ + kcol + 1];
        #pragma unroll
        for (int mt = 0; mt < 2; mt++) {
            int q = q0 + wm * 32 + mt * 16 + g;
            int jq = jc - (q - q0);
            C[mt][nt][0] = C[mt][nt][0] * 0.125f + sLut[jq]     + mv0;
            C[mt][nt][1] = C[mt][nt][1] * 0.125f + sLut[jq + 1] + mv1;
            *(float2*)&wbase[(size_t)q * S_ + kcol] = make_float2(C[mt][nt][0], C[mt][nt][1]);
            int jq2 = jq - 8;
            C[mt][nt][2] = C[mt][nt][2] * 0.125f + sLut[jq2]     + mv0;
            C[mt][nt][3] = C[mt][nt][3] * 0.125f + sLut[jq2 + 1] + mv1;
            *(float2*)&wbase[(size_t)(q + 8) * S_ + kcol] = make_float2(C[mt][nt][2], C[mt][nt][3]);
        }
    }

    // per-row (128-col block) max & sumexp
    float mxv[4], smv[4];
    #pragma unroll
    for (int ri = 0; ri < 4; ri++) {
        int mt = ri >> 1, hf = ri & 1;
        float m = -3.4e38f;
        #pragma unroll
        for (int nt = 0; nt < 8; nt++) {
            m = fmaxf(m, C[mt][nt][hf * 2]);
            m = fmaxf(m, C[mt][nt][hf * 2 + 1]);
        }
        m = fmaxf(m, __shfl_xor_sync(0xffffffffu, m, 1));
        m = fmaxf(m, __shfl_xor_sync(0xffffffffu, m, 2));
        float s = 0.f;
        #pragma unroll
        for (int nt = 0; nt < 8; nt++) {
            s += fast_exp(C[mt][nt][hf * 2]     - m);
            s += fast_exp(C[mt][nt][hf * 2 + 1] - m);
        }
        s += __shfl_xor_sync(0xffffffffu, s, 1);
        s += __shfl_xor_sync(0xffffffffu, s, 2);
        mxv[ri] = m; smv[ri] = s;
    }
    __syncthreads();

    float* sMax = (float*)smu;          // [128][2]
    float* sSum = sMax + 256;
    if (tg == 0) {
        #pragma unroll
        for (int ri = 0; ri < 4; ri++) {
            int rl = wm * 32 + (ri >> 1) * 16 + (ri & 1) * 8 + g;
            sMax[rl * 2 + wn] = mxv[ri];
            sSum[rl * 2 + wn] = smv[ri];
        }
    }
    __syncthreads();
    if (t < 128) {
        float m0 = sMax[t * 2], m1 = sMax[t * 2 + 1];
        float M = fmaxf(m0, m1);
        float Sv = sSum[t * 2] * fast_exp(m0 - M) + sSum[t * 2 + 1] * fast_exp(m1 - M);
        g_stats[((size_t)bh * S_ + q0 + t) * QBLK + blockIdx.x] = make_float2(M, Sv);
    }
}

// ---------------------------------------------------------------------------
// Kernel 2: merge 16 k-block stats per row -> (rowmax, 1/rowsum). 1 warp/row.
// ---------------------------------------------------------------------------
__global__ __launch_bounds__(256) void reduce_kernel()
{
    int t = threadIdx.x;
    int wid = t >> 5, lane = t & 31;
    int row = blockIdx.x * 8 + wid;
    float2 st = (lane < QBLK) ? g_stats[(size_t)row * QBLK + lane]
                              : make_float2(-3.4e38f, 0.f);
    float M = st.x;
    #pragma unroll
    for (int o = 8; o; o >>= 1) M = fmaxf(M, __shfl_xor_sync(0xffffffffu, M, o));
    M = fmaxf(M, __shfl_xor_sync(0xffffffffu, M, 16));
    float Sv = st.y * fast_exp(st.x - M);
    #pragma unroll
    for (int o = 16; o; o >>= 1) Sv += __shfl_xor_sync(0xffffffffu, Sv, o);
    if (lane == 0) g_rowstats[row] = make_float2(M, 1.0f / Sv);
}

// ---------------------------------------------------------------------------
// Kernel 3: fused softmax-apply + P@V, cp.async double-buffered, ldmatrix.
// ---------------------------------------------------------------------------
#define PSTR 36
#define RAWSTR 68
#define OFF_RAW   0
#define OFF_PH    (2 * 64 * RAWSTR)
#define OFF_PL    (OFF_PH + 64 * PSTR)
#define OFF_VH    (OFF_PL + 64 * PSTR)
#define OFF_VL    (OFF_VH + 2 * 64 * PSTR)
#define OFF_ST    (OFF_VL + 2 * 64 * PSTR)
#define AV_SMEM   ((OFF_ST + 128) * 4)

__global__ __launch_bounds__(256) void av_kernel(
    float* __restrict__ W, const float* __restrict__ V, float* __restrict__ out)
{
    extern __shared__ unsigned smu[];
    float*    rawW = (float*)smu;
    unsigned* Ph   = smu + OFF_PH;
    unsigned* Pl   = smu + OFF_PL;
    float*    sM   = (float*)(smu + OFF_ST);
    float*    sI   = sM + 64;

    int bh = blockIdx.y;
    int q0 = blockIdx.x * 64;

    float* Wp = W + OUT_OFF + (size_t)bh * S_ * S_;

    int t = threadIdx.x;
    int w = t >> 5, l = t & 31, g = l >> 2, tg = l & 3;
    int wm = w & 3, wn = w >> 2;

    unsigned sbase = (unsigned)__cvta_generic_to_shared(smu);

    int lq = l & 7, lh8 = (l >> 3) & 1, lc = (l >> 4);
    int qd = l >> 3;
    unsigned aoff = ((wm * 16 + lh8 * 8 + lq) * PSTR + lc * 4) * 4;
    unsigned boff = ((wn * 32 + (qd >> 1) * 8 + lq) * PSTR + (qd & 1) * 4) * 4;

    if (t < 64) {
        float2 rs = g_rowstats[(size_t)bh * S_ + q0 + t];
        sM[t] = rs.x; sI[t] = rs.y;
    }

    // prefetch chunk 0 into stage 0
    {
        #pragma unroll
        for (int i = 0; i < 4; i++) {
            int idx = t + i * 256;
            int r = idx >> 4, c4 = idx & 15;
            cpa16(sbase + (OFF_RAW + r * RAWSTR + c4 * 4) * 4,
                  &Wp[(size_t)(q0 + r) * S_ + c4 * 4]);
        }
        unsigned vb = (unsigned)bh * KBLK * 64 * 32;
        #pragma unroll
        for (int i = 0; i < 2; i++) {
            int idx = t + i * 256;
            int d = idx >> 3, sg = idx & 7;
            cpa16(sbase + (OFF_VH + d * PSTR + sg * 4) * 4, &g_Vth[vb + d * 32 + sg * 4]);
            cpa16(sbase + (OFF_VL + d * PSTR + sg * 4) * 4, &g_Vtl[vb + d * 32 + sg * 4]);
        }
        cpa_commit();
    }

    float C[4][4] = {};

    for (int kci = 0; kci < KBLK; kci++) {
        int kc = kci * 64;
        int st = kci & 1;
        cpa_wait0();
        __syncthreads();

        if (kci + 1 < KBLK) {
            int s = (kci + 1) & 1;
            #pragma unroll
            for (int i = 0; i < 4; i++) {
                int idx = t + i * 256;
                int r = idx >> 4, c4 = idx & 15;
                cpa16(sbase + (OFF_RAW + s * 64 * RAWSTR + r * RAWSTR + c4 * 4) * 4,
                      &Wp[(size_t)(q0 + r) * S_ + kc + 64 + c4 * 4]);
            }
            unsigned vb = ((unsigned)bh * KBLK + kci + 1) * 64 * 32;
            #pragma unroll
            for (int i = 0; i < 2; i++) {
                int idx = t + i * 256;
                int d = idx >> 3, sg = idx & 7;
                cpa16(sbase + (OFF_VH + s * 64 * PSTR + d * PSTR + sg * 4) * 4,
                      &g_Vth[vb + d * 32 + sg * 4]);
                cpa16(sbase + (OFF_VL + s * 64 * PSTR + d * PSTR + sg * 4) * 4,
                      &g_Vtl[vb + d * 32 + sg * 4]);
            }
            cpa_commit();
        }

        // fill P: softmax-apply from smem raw, write back, pack
        #pragma unroll
        for (int i = 0; i < 4; i++) {
            int idx = t + i * 256;
            int q = idx >> 4, f4 = idx & 15;
            float4 wv = *(const float4*)&rawW[st * 64 * RAWSTR + q * RAWSTR + f4 * 4];
            float Mc = sM[q] * LOG2E, I = sI[q];
            float p0 = ex2f(fmaf(wv.x, LOG2E, -Mc)) * I;
            float p1 = ex2f(fmaf(wv.y, LOG2E, -Mc)) * I;
            float p2 = ex2f(fmaf(wv.z, LOG2E, -Mc)) * I;
            float p3 = ex2f(fmaf(wv.w, LOG2E, -Mc)) * I;
            *(float4*)&Wp[(size_t)(q0 + q) * S_ + kc + f4 * 4] = make_float4(p0, p1, p2, p3);
            unsigned h0, l0, h1, l1;
            split_pack(p0, p1, h0, l0);
            split_pack(p2, p3, h1, l1);
            *(uint2*)&Ph[q * PSTR + 2 * f4] = make_uint2(h0, h1);
            *(uint2*)&Pl[q * PSTR + 2 * f4] = make_uint2(l0, l1);
        }
        __syncthreads();

        unsigned vhb = (OFF_VH + st * 64 * PSTR) * 4;
        unsigned vlb = (OFF_VL + st * 64 * PSTR) * 4;
        #pragma unroll
        for (int ks = 0; ks < 4; ks++) {
            unsigned ah[4], al[4];
            ldm4(ah, sbase + OFF_PH * 4 + aoff + ks * 32);
            ldm4(al, sbase + OFF_PL * 4 + aoff + ks * 32);
            #pragma unroll
            for (int ntp = 0; ntp < 2; ntp++) {
                unsigned bhf[4], blf[4];
                ldm4(bhf, sbase + vhb + boff + ntp * (16 * PSTR * 4) + ks * 32);
                ldm4(blf, sbase + vlb + boff + ntp * (16 * PSTR * 4) + ks * 32);
                mma16(C[2 * ntp],     ah, bhf);
                mma16(C[2 * ntp],     ah, blf);
                mma16(C[2 * ntp],     al, bhf);
                mma16(C[2 * ntp + 1], ah, bhf + 2);
                mma16(C[2 * ntp + 1], ah, blf + 2);
                mma16(C[2 * ntp + 1], al, bhf + 2);
            }
        }
        __syncthreads();
    }

    #pragma unroll
    for (int nt = 0; nt < 4; nt++) {
        int d = wn * 32 + nt * 8 + 2 * tg;
        int q = q0 + wm * 16 + g;
        *(float2*)&out[((size_t)bh * S_ + q) * D_ + d]     = make_float2(C[nt][0], C[nt][1]);
        *(float2*)&out[((size_t)bh * S_ + q + 8) * D_ + d] = make_float2(C[nt][2], C[nt][3]);
    }
}

// ---------------------------------------------------------------------------
extern "C" void kernel_launch(void* const* d_in, const int* in_sizes, int n_in,
                              void* d_out, int out_size)
{
    const float* Q    = (const float*)d_in[0];
    const float* K    = (const float*)d_in[1];
    const float* V    = (const float*)d_in[2];
    const int*   mask = (const int*)d_in[3];
    const float* bt   = (const float*)d_in[4];
    float* out = (float*)d_out;

    cudaFuncSetAttribute(logits_kernel, cudaFuncAttributeMaxDynamicSharedMemorySize, L_SMEM);
    cudaFuncSetAttribute(av_kernel,     cudaFuncAttributeMaxDynamicSharedMemorySize, AV_SMEM);

    bias_lut_kernel<<<32, 1024>>>(bt);

    dim3 gv(KBLK, BH_);
    v_prep_kernel<<<gv, 256>>>(V);

    dim3 g1(S_ / 128, S_ / 128, BH_);   // (16, 16, 16)
    logits_kernel<<<g1, 256, L_SMEM>>>(Q, K, mask, out);

    reduce_kernel<<<BH_ * S_ / 8, 256>>>();

    dim3 g2(S_ / 64, BH_);              // (32, 16)
    av_kernel<<<g2, 256, AV_SMEM>>>(out, V, out);
}